// round 2
// baseline (speedup 1.0000x reference)
#include <cuda_runtime.h>
#include <cstdint>

// ============================================================================
// ZyboGPT hw-accurate quantized transformer forward, bit-exact integer impl.
// B=4 T=1024 D=64 H=2 HD=32 DFF=256 L=4 V=8192
// ============================================================================

#define NTOK   4096      // B*T
#define TSEQ   1024
#define NH     2
#define DFF    256
#define VOC    8192
#define WPL    12288     // packed u32 words per layer: qkv[0,3072) o[3072,4096) up[4096,8192) down[8192,12288)

// ---- scratch (device globals; no allocations allowed) ----
__device__ __align__(16) int8_t  g_x [NTOK*64];
__device__ __align__(16) int8_t  g_q [NTOK*64];
__device__ __align__(16) int8_t  g_k [NTOK*64];
__device__ __align__(16) int8_t  g_v [NTOK*64];
__device__ __align__(16) int8_t  g_vt[8*32*1024];   // [b*H+h][d][t]
__device__ __align__(16) int8_t  g_a [NTOK*64];
__device__ __align__(16) int8_t  g_u [NTOK*DFF];
__device__ __align__(16) int8_t  g_h [NTOK*64];
__device__ __align__(16) uint32_t g_wter[4*WPL];
__device__ __align__(16) int8_t  g_ehi[VOC*64];
__device__ __align__(16) uint8_t g_elo[VOC*64];

// ---- dp4a helpers (mixed sign via PTX) ----
__device__ __forceinline__ int dp4a_ss(int a, int b, int c) { return __dp4a(a, b, c); }
__device__ __forceinline__ int dp4a_us(unsigned a, int b, int c) {
    int d; asm("dp4a.u32.s32 %0, %1, %2, %3;" : "=r"(d) : "r"(a), "r"(b), "r"(c)); return d;
}
__device__ __forceinline__ int dp4a_su(int a, unsigned b, int c) {
    int d; asm("dp4a.s32.u32 %0, %1, %2, %3;" : "=r"(d) : "r"(a), "r"(b), "r"(c)); return d;
}

__device__ __forceinline__ int iclamp(int v, int lo, int hi) { return min(max(v, lo), hi); }

// ============================================================================
// Weight ternarization: scale = max(mean|w|,1e-5); w_t = clamp(round(w/scale),-1,1)
// 24 blocks: blockIdx.x = layer*6 + {0:q,1:k,2:v,3:o,4:up,5:down}
// ============================================================================
__global__ void prep_w_k(const float* __restrict__ qw, const float* __restrict__ kw,
                         const float* __restrict__ vw, const float* __restrict__ ow,
                         const float* __restrict__ upw, const float* __restrict__ dnw) {
    int id = blockIdx.x, l = id / 6, mt = id % 6, tid = threadIdx.x;
    const float* w; int N; uint32_t* dst;
    switch (mt) {
        case 0: w = qw  + l*4096;  N = 4096;  dst = g_wter + l*WPL + 0;    break;
        case 1: w = kw  + l*4096;  N = 4096;  dst = g_wter + l*WPL + 1024; break;
        case 2: w = vw  + l*4096;  N = 4096;  dst = g_wter + l*WPL + 2048; break;
        case 3: w = ow  + l*4096;  N = 4096;  dst = g_wter + l*WPL + 3072; break;
        case 4: w = upw + l*16384; N = 16384; dst = g_wter + l*WPL + 4096; break;
        default:w = dnw + l*16384; N = 16384; dst = g_wter + l*WPL + 8192; break;
    }
    __shared__ float rs[256];
    float s = 0.0f;
    for (int i = tid; i < N; i += 256) s += fabsf(w[i]);
    rs[tid] = s; __syncthreads();
    for (int st = 128; st > 0; st >>= 1) {
        if (tid < st) rs[tid] += rs[tid + st];
        __syncthreads();
    }
    float scale = fmaxf(__fdiv_rn(rs[0], (float)N), 1e-5f);
    for (int wi = tid; wi < N / 4; wi += 256) {
        uint32_t pk = 0;
        #pragma unroll
        for (int j = 0; j < 4; j++) {
            int tv = (int)rintf(__fdiv_rn(w[wi*4 + j], scale));
            tv = iclamp(tv, -1, 1);
            pk |= ((uint32_t)(tv & 255)) << (8 * j);
        }
        dst[wi] = pk;
    }
}

// emb_q = clamp(round(tok_emb*1024), -32768, 32767); split into hi s8 / lo u8
__global__ void prep_emb_k(const float* __restrict__ temb) {
    int i = blockIdx.x * blockDim.x + threadIdx.x;
    if (i >= VOC * 64) return;
    int q = iclamp((int)rintf(__fmul_rn(temb[i], 1024.0f)), -32768, 32767);
    g_ehi[i] = (int8_t)(q >> 8);
    g_elo[i] = (uint8_t)(q & 255);
}

// x = wrap8( floor((tok_q + pos_q)/8) )
__global__ void embed_k(const int* __restrict__ tokens, const float* __restrict__ temb,
                        const float* __restrict__ pemb) {
    int i = blockIdx.x * blockDim.x + threadIdx.x;
    if (i >= NTOK * 64) return;
    int t = i >> 6, d = i & 63;
    int tok = tokens[t];
    int tq = iclamp((int)rintf(__fmul_rn(temb[tok*64 + d], 1024.0f)), -32768, 32767);
    int pq = iclamp((int)rintf(__fmul_rn(pemb[(t & 1023)*64 + d], 1024.0f)), -32768, 32767);
    g_x[i] = (int8_t)((tq + pq) >> 3);
}

// ============================================================================
// rmsnorm (hw LUT version) -> int8 row in shared memory. Block-per-token.
// ============================================================================
__device__ __forceinline__ void rmsnorm_to_smem(const int8_t* __restrict__ xrow,
                                                const float* __restrict__ nw,
                                                uint8_t* hs, int* red) {
    int d = threadIdx.x;
    if (d < 64) {
        int xi = xrow[d];
        int sq = xi * xi;
        #pragma unroll
        for (int o = 16; o; o >>= 1) sq += __shfl_xor_sync(0xffffffffu, sq, o);
        if ((d & 31) == 0) red[d >> 5] = sq;
    }
    __syncthreads();
    if (d < 64) {
        int sumsq = red[0] + red[1];
        int lut = min((sumsq >> 6) >> 6, 255);         // clip(mean_sq>>6, 0, 255)
        float bc = (float)(lut * 64 + 32);             // >= 32 so max(,1) moot
        int inv = iclamp((int)rintf(__fdiv_rn(16384.0f, __fsqrt_rn(bc))), 0, 16383);
        int xi = xrow[d];
        int p1 = (xi * inv) >> 8;                      // floor
        float wc = fminf(fmaxf(nw[d], -2.0f), 2.0f);
        int g = iclamp((int)rintf(__fmul_rn(wc, 1024.0f)), -32768, 32767);
        // replicate JAX fp32: floor( fl(p1*g) * 2^-10 )
        float prod = __fmul_rn(__int2float_rn(p1), __int2float_rn(g));
        int y = (int)floorf(__fmul_rn(prod, 0.0009765625f));
        hs[d] = (uint8_t)iclamp(y, -128, 127);
    }
    __syncthreads();
}

// rmsnorm + fused QKV bitlinear. 192 threads. Also writes transposed V.
__global__ void norm_qkv_k(const float* __restrict__ anw, int l) {
    __shared__ __align__(16) uint8_t hs[64];
    __shared__ int red[2];
    int t = blockIdx.x;
    rmsnorm_to_smem(g_x + t*64, anw + l*64, hs, red);
    int o = threadIdx.x;                               // 0..191 (q:0-63 k:64-127 v:128-191)
    const uint32_t* wt = g_wter + l*WPL + o*16;
    const uint32_t* h4 = (const uint32_t*)hs;
    int acc = 0;
    #pragma unroll
    for (int i = 0; i < 16; i++) acc = dp4a_ss((int)h4[i], (int)wt[i], acc);
    int y = iclamp(acc >> 6, -128, 127);
    if (o < 64) g_q[t*64 + o] = (int8_t)y;
    else if (o < 128) g_k[t*64 + (o - 64)] = (int8_t)y;
    else {
        int oo = o - 128;
        g_v[t*64 + oo] = (int8_t)y;
        int b = t >> 10, tt = t & 1023;
        g_vt[((b*NH + (oo >> 5))*32 + (oo & 31))*1024 + tt] = (int8_t)y;
    }
}

// rmsnorm + fused up-proj (relu). 256 threads.
__global__ void norm_up_k(const float* __restrict__ fnw, int l) {
    __shared__ __align__(16) uint8_t hs[64];
    __shared__ int red[2];
    int t = blockIdx.x;
    rmsnorm_to_smem(g_x + t*64, fnw + l*64, hs, red);
    int o = threadIdx.x;
    const uint32_t* wt = g_wter + l*WPL + 4096 + o*16;
    const uint32_t* h4 = (const uint32_t*)hs;
    int acc = 0;
    #pragma unroll
    for (int i = 0; i < 16; i++) acc = dp4a_ss((int)h4[i], (int)wt[i], acc);
    int y = iclamp(acc >> 6, -128, 127);
    g_u[t*DFF + o] = (int8_t)max(y, 0);
}

// bitlinear + residual-add with int8 wraparound. 64 threads. SRC=0: g_a, SRC=1: g_u
template<int IN, int SRC>
__global__ void linear_res_k(int woff, int l) {
    __shared__ __align__(16) uint32_t xs[IN/4];
    int t = blockIdx.x, o = threadIdx.x;
    const int8_t* in = (SRC == 0) ? g_a : g_u;
    if (o < IN/4) xs[o] = ((const uint32_t*)(in + t*IN))[o];
    __syncthreads();
    const uint32_t* wt = g_wter + l*WPL + woff + o*(IN/4);
    int acc = 0;
    #pragma unroll
    for (int i = 0; i < IN/4; i++) acc = dp4a_ss((int)xs[i], (int)wt[i], acc);
    int y = iclamp(acc >> 6, -128, 127);
    g_x[t*64 + o] = (int8_t)(g_x[t*64 + o] + y);       // wrap-around int8
}

// final rmsnorm -> g_h
__global__ void final_norm_k(const float* __restrict__ fnw) {
    __shared__ __align__(16) uint8_t hs[64];
    __shared__ int red[2];
    int t = blockIdx.x;
    rmsnorm_to_smem(g_x + t*64, fnw, hs, red);
    if (threadIdx.x < 64) g_h[t*64 + threadIdx.x] = (int8_t)hs[threadIdx.x];
}

// ============================================================================
// Attention: 1 warp per query, 8 queries per block, grid (T/8, B*H).
// Scores & piecewise-exp in smem; probs packed u8; PV via dp4a vs transposed V.
// ============================================================================
__global__ void attn_k() {
    __shared__ int sc[8][1024];                        // scores -> ea
    __shared__ __align__(4) uint8_t pp[8][1024];       // probs u8
    int w = threadIdx.x >> 5, lane = threadIdx.x & 31;
    int bh = blockIdx.y;                               // b*H + h
    int b = bh >> 1, h = bh & 1;
    int qi = blockIdx.x * 8 + w;
    int tq = b*TSEQ + qi;

    const uint32_t* qrow = (const uint32_t*)(g_q + tq*64 + h*32);
    uint32_t qr[8];
    #pragma unroll
    for (int j = 0; j < 8; j++) qr[j] = qrow[j];

    // P1: scores (masked = -32767), track max
    int mymax = -0x7fffffff;
    for (int kb = 0; kb < 32; kb++) {
        int key = kb*32 + lane;
        int s;
        if (key <= qi) {
            const uint32_t* krow = (const uint32_t*)(g_k + (b*TSEQ + key)*64 + h*32);
            int acc = 0;
            #pragma unroll
            for (int j = 0; j < 8; j++) acc = dp4a_ss((int)qr[j], (int)krow[j], acc);
            // replicate JAX fp32: floor( fl(qk*45) * 2^-8 )
            float f = __fmul_rn(__int2float_rn(acc), 45.0f);
            s = (int)floorf(__fmul_rn(f, 0.00390625f));
        } else {
            s = -32767;
        }
        sc[w][key] = s;
        mymax = max(mymax, s);
    }
    #pragma unroll
    for (int o = 16; o; o >>= 1) mymax = max(mymax, __shfl_xor_sync(0xffffffffu, mymax, o));
    int m = mymax;

    // P2: piecewise-linear exp, sum
    __syncwarp();
    int lsum = 0;
    for (int kb = 0; kb < 32; kb++) {
        int key = kb*32 + lane;
        int sh = sc[w][key] - m;
        int ea;
        if (sh >= -3)       ea = 256 + sh*64;
        else if (sh >= -8)  ea = 64 + (sh + 3)*11;
        else if (sh >= -24) ea = sh + 24;
        else                ea = 0;
        sc[w][key] = ea;
        lsum += ea;
    }
    #pragma unroll
    for (int o = 16; o; o >>= 1) lsum += __shfl_xor_sync(0xffffffffu, lsum, o);
    float fs = (float)max(lsum, 1);

    // P3a: probs = clamp(round(ea/s*255), 0, 255)  (IEEE fp32 div+mul, rint)
    __syncwarp();
    for (int kb = 0; kb < 32; kb++) {
        int key = kb*32 + lane;
        float p = __fmul_rn(__fdiv_rn((float)sc[w][key], fs), 255.0f);
        pp[w][key] = (uint8_t)iclamp((int)rintf(p), 0, 255);
    }
    __syncwarp();

    // P3b: pv[d] = sum_k p[k]*v[k][d]  (lane = dim d), dp4a u8 x s8
    const uint32_t* vtd = (const uint32_t*)(g_vt + (bh*32 + lane)*1024);
    const uint32_t* p4 = (const uint32_t*)pp[w];
    // masked probs are 0 except pathological all-below case; handle both
    int jmax = (qi < 1023 && m <= -32743) ? 256 : ((qi >> 2) + 1);
    int acc = 0;
    for (int j = 0; j < jmax; j++) acc = dp4a_us(p4[j], (int)vtd[j], acc);
    g_a[tq*64 + h*32 + lane] = (int8_t)(acc >> 8);     // floor >>8, then wrap8
}

// ============================================================================
// Logits: x(int8) . emb_q(Q5.10 split hi s8 / lo u8), scale 2^-13 exact.
// Block: 256 threads = 256 vocab cols x 16-token tile. grid (V/256, NTOK/16).
// ============================================================================
__global__ void logits_k(float* __restrict__ out) {
    __shared__ __align__(16) uint32_t xs[16][16];
    int tid = threadIdx.x;
    int tb = blockIdx.y * 16;
    xs[tid >> 4][tid & 15] = ((const uint32_t*)(g_h + (tb + (tid >> 4))*64))[tid & 15];
    __syncthreads();
    int v = blockIdx.x * 256 + tid;
    uint32_t hi[16], lo[16];
    const uint32_t* hp = (const uint32_t*)(g_ehi + v*64);
    const uint32_t* lp = (const uint32_t*)(g_elo + v*64);
    #pragma unroll
    for (int i = 0; i < 16; i++) { hi[i] = hp[i]; lo[i] = lp[i]; }
    #pragma unroll 4
    for (int t = 0; t < 16; t++) {
        int ah = 0, al = 0;
        #pragma unroll
        for (int i = 0; i < 16; i++) {
            uint32_t xw = xs[t][i];
            ah = dp4a_ss((int)xw, (int)hi[i], ah);
            al = dp4a_su((int)xw, lo[i], al);
        }
        int dot = ah * 256 + al;                       // exact int32
        out[(tb + t)*VOC + v] = __fmul_rn(__int2float_rn(dot), 1.220703125e-4f); // *2^-13
    }
}

// ============================================================================
extern "C" void kernel_launch(void* const* d_in, const int* in_sizes, int n_in,
                              void* d_out, int out_size) {
    const int*   tokens  = (const int*)  d_in[0];
    const float* tok_emb = (const float*)d_in[1];
    const float* pos_emb = (const float*)d_in[2];
    const float* anw     = (const float*)d_in[3];
    const float* qw      = (const float*)d_in[4];
    const float* kw      = (const float*)d_in[5];
    const float* vw      = (const float*)d_in[6];
    const float* ow      = (const float*)d_in[7];
    const float* fnw     = (const float*)d_in[8];
    const float* upw     = (const float*)d_in[9];
    const float* dnw     = (const float*)d_in[10];
    const float* finw    = (const float*)d_in[11];
    float* out = (float*)d_out;

    prep_w_k<<<24, 256>>>(qw, kw, vw, ow, upw, dnw);
    prep_emb_k<<<(VOC*64)/256, 256>>>(tok_emb);
    embed_k<<<(NTOK*64)/256, 256>>>(tokens, tok_emb, pos_emb);

    for (int l = 0; l < 4; l++) {
        norm_qkv_k<<<NTOK, 192>>>(anw, l);
        attn_k<<<dim3(TSEQ/8, 4*NH), 256>>>();
        linear_res_k<64, 0><<<NTOK, 64>>>(3072, l);    // o-proj + residual
        norm_up_k<<<NTOK, 256>>>(fnw, l);
        linear_res_k<256, 1><<<NTOK, 64>>>(8192, l);   // down-proj + residual
    }
    final_norm_k<<<NTOK, 64>>>(finw);
    logits_k<<<dim3(VOC/256, NTOK/16), 256>>>(out);
}

// round 4
// speedup vs baseline: 1.0277x; 1.0277x over previous
#include <cuda_runtime.h>
#include <cstdint>

// ============================================================================
// ZyboGPT hw-accurate quantized transformer forward, bit-exact integer impl.
// B=4 T=1024 D=64 H=2 HD=32 DFF=256 L=4 V=8192
// R2: logits GEMM moved from dp4a (fma pipe) to mma.sync m16n8k32 IMMA.
// ============================================================================

#define NTOK   4096      // B*T
#define TSEQ   1024
#define NH     2
#define DFF    256
#define VOC    8192
#define WPL    12288     // packed u32 words per layer: qkv[0,3072) o[3072,4096) up[4096,8192) down[8192,12288)

// ---- scratch (device globals; no allocations allowed) ----
__device__ __align__(16) int8_t  g_x [NTOK*64];
__device__ __align__(16) int8_t  g_q [NTOK*64];
__device__ __align__(16) int8_t  g_k [NTOK*64];
__device__ __align__(16) int8_t  g_v [NTOK*64];
__device__ __align__(16) int8_t  g_vt[8*32*1024];   // [b*H+h][d][t]
__device__ __align__(16) int8_t  g_a [NTOK*64];
__device__ __align__(16) int8_t  g_u [NTOK*DFF];
__device__ __align__(16) int8_t  g_h [NTOK*64];
__device__ __align__(16) uint32_t g_wter[4*WPL];
__device__ __align__(16) int8_t  g_ehi[VOC*64];
__device__ __align__(16) uint8_t g_elo[VOC*64];

// ---- dp4a helpers (mixed sign via PTX) ----
__device__ __forceinline__ int dp4a_ss(int a, int b, int c) { return __dp4a(a, b, c); }
__device__ __forceinline__ int dp4a_us(unsigned a, int b, int c) {
    int d; asm("dp4a.u32.s32 %0, %1, %2, %3;" : "=r"(d) : "r"(a), "r"(b), "r"(c)); return d;
}

__device__ __forceinline__ int iclamp(int v, int lo, int hi) { return min(max(v, lo), hi); }

// ---- IMMA wrappers: m16n8k32, row.col, s32 accum ----
__device__ __forceinline__ void mma_s8s8(int* c, const uint32_t* a, const uint32_t* b) {
    asm volatile("mma.sync.aligned.m16n8k32.row.col.s32.s8.s8.s32 "
        "{%0,%1,%2,%3}, {%4,%5,%6,%7}, {%8,%9}, {%0,%1,%2,%3};"
        : "+r"(c[0]), "+r"(c[1]), "+r"(c[2]), "+r"(c[3])
        : "r"(a[0]), "r"(a[1]), "r"(a[2]), "r"(a[3]), "r"(b[0]), "r"(b[1]));
}
__device__ __forceinline__ void mma_s8u8(int* c, const uint32_t* a, const uint32_t* b) {
    asm volatile("mma.sync.aligned.m16n8k32.row.col.s32.s8.u8.s32 "
        "{%0,%1,%2,%3}, {%4,%5,%6,%7}, {%8,%9}, {%0,%1,%2,%3};"
        : "+r"(c[0]), "+r"(c[1]), "+r"(c[2]), "+r"(c[3])
        : "r"(a[0]), "r"(a[1]), "r"(a[2]), "r"(a[3]), "r"(b[0]), "r"(b[1]));
}

// ============================================================================
// Weight ternarization: scale = max(mean|w|,1e-5); w_t = clamp(round(w/scale),-1,1)
// ============================================================================
__global__ void prep_w_k(const float* __restrict__ qw, const float* __restrict__ kw,
                         const float* __restrict__ vw, const float* __restrict__ ow,
                         const float* __restrict__ upw, const float* __restrict__ dnw) {
    int id = blockIdx.x, l = id / 6, mt = id % 6, tid = threadIdx.x;
    const float* w; int N; uint32_t* dst;
    switch (mt) {
        case 0: w = qw  + l*4096;  N = 4096;  dst = g_wter + l*WPL + 0;    break;
        case 1: w = kw  + l*4096;  N = 4096;  dst = g_wter + l*WPL + 1024; break;
        case 2: w = vw  + l*4096;  N = 4096;  dst = g_wter + l*WPL + 2048; break;
        case 3: w = ow  + l*4096;  N = 4096;  dst = g_wter + l*WPL + 3072; break;
        case 4: w = upw + l*16384; N = 16384; dst = g_wter + l*WPL + 4096; break;
        default:w = dnw + l*16384; N = 16384; dst = g_wter + l*WPL + 8192; break;
    }
    __shared__ float rs[256];
    float s = 0.0f;
    for (int i = tid; i < N; i += 256) s += fabsf(w[i]);
    rs[tid] = s; __syncthreads();
    for (int st = 128; st > 0; st >>= 1) {
        if (tid < st) rs[tid] += rs[tid + st];
        __syncthreads();
    }
    float scale = fmaxf(__fdiv_rn(rs[0], (float)N), 1e-5f);
    for (int wi = tid; wi < N / 4; wi += 256) {
        uint32_t pk = 0;
        #pragma unroll
        for (int j = 0; j < 4; j++) {
            int tv = (int)rintf(__fdiv_rn(w[wi*4 + j], scale));
            tv = iclamp(tv, -1, 1);
            pk |= ((uint32_t)(tv & 255)) << (8 * j);
        }
        dst[wi] = pk;
    }
}

// emb_q = clamp(round(tok_emb*1024), -32768, 32767); split into hi s8 / lo u8
__global__ void prep_emb_k(const float* __restrict__ temb) {
    int i = blockIdx.x * blockDim.x + threadIdx.x;
    if (i >= VOC * 64) return;
    int q = iclamp((int)rintf(__fmul_rn(temb[i], 1024.0f)), -32768, 32767);
    g_ehi[i] = (int8_t)(q >> 8);
    g_elo[i] = (uint8_t)(q & 255);
}

// x = wrap8( floor((tok_q + pos_q)/8) )
__global__ void embed_k(const int* __restrict__ tokens, const float* __restrict__ temb,
                        const float* __restrict__ pemb) {
    int i = blockIdx.x * blockDim.x + threadIdx.x;
    if (i >= NTOK * 64) return;
    int t = i >> 6, d = i & 63;
    int tok = tokens[t];
    int tq = iclamp((int)rintf(__fmul_rn(temb[tok*64 + d], 1024.0f)), -32768, 32767);
    int pq = iclamp((int)rintf(__fmul_rn(pemb[(t & 1023)*64 + d], 1024.0f)), -32768, 32767);
    g_x[i] = (int8_t)((tq + pq) >> 3);
}

// ============================================================================
// rmsnorm (hw LUT version) -> int8 row in shared memory. Block-per-token.
// ============================================================================
__device__ __forceinline__ void rmsnorm_to_smem(const int8_t* __restrict__ xrow,
                                                const float* __restrict__ nw,
                                                uint8_t* hs, int* red) {
    int d = threadIdx.x;
    if (d < 64) {
        int xi = xrow[d];
        int sq = xi * xi;
        #pragma unroll
        for (int o = 16; o; o >>= 1) sq += __shfl_xor_sync(0xffffffffu, sq, o);
        if ((d & 31) == 0) red[d >> 5] = sq;
    }
    __syncthreads();
    if (d < 64) {
        int sumsq = red[0] + red[1];
        int lut = min((sumsq >> 6) >> 6, 255);         // clip(mean_sq>>6, 0, 255)
        float bc = (float)(lut * 64 + 32);             // >= 32 so max(,1) moot
        int inv = iclamp((int)rintf(__fdiv_rn(16384.0f, __fsqrt_rn(bc))), 0, 16383);
        int xi = xrow[d];
        int p1 = (xi * inv) >> 8;                      // floor
        float wc = fminf(fmaxf(nw[d], -2.0f), 2.0f);
        int g = iclamp((int)rintf(__fmul_rn(wc, 1024.0f)), -32768, 32767);
        float prod = __fmul_rn(__int2float_rn(p1), __int2float_rn(g));
        int y = (int)floorf(__fmul_rn(prod, 0.0009765625f));
        hs[d] = (uint8_t)iclamp(y, -128, 127);
    }
    __syncthreads();
}

// rmsnorm + fused QKV bitlinear. 192 threads. Also writes transposed V.
__global__ void norm_qkv_k(const float* __restrict__ anw, int l) {
    __shared__ __align__(16) uint8_t hs[64];
    __shared__ int red[2];
    int t = blockIdx.x;
    rmsnorm_to_smem(g_x + t*64, anw + l*64, hs, red);
    int o = threadIdx.x;                               // 0..191 (q:0-63 k:64-127 v:128-191)
    const uint32_t* wt = g_wter + l*WPL + o*16;
    const uint32_t* h4 = (const uint32_t*)hs;
    int acc = 0;
    #pragma unroll
    for (int i = 0; i < 16; i++) acc = dp4a_ss((int)h4[i], (int)wt[i], acc);
    int y = iclamp(acc >> 6, -128, 127);
    if (o < 64) g_q[t*64 + o] = (int8_t)y;
    else if (o < 128) g_k[t*64 + (o - 64)] = (int8_t)y;
    else {
        int oo = o - 128;
        g_v[t*64 + oo] = (int8_t)y;
        int b = t >> 10, tt = t & 1023;
        g_vt[((b*NH + (oo >> 5))*32 + (oo & 31))*1024 + tt] = (int8_t)y;
    }
}

// rmsnorm + fused up-proj (relu). 256 threads.
__global__ void norm_up_k(const float* __restrict__ fnw, int l) {
    __shared__ __align__(16) uint8_t hs[64];
    __shared__ int red[2];
    int t = blockIdx.x;
    rmsnorm_to_smem(g_x + t*64, fnw + l*64, hs, red);
    int o = threadIdx.x;
    const uint32_t* wt = g_wter + l*WPL + 4096 + o*16;
    const uint32_t* h4 = (const uint32_t*)hs;
    int acc = 0;
    #pragma unroll
    for (int i = 0; i < 16; i++) acc = dp4a_ss((int)h4[i], (int)wt[i], acc);
    int y = iclamp(acc >> 6, -128, 127);
    g_u[t*DFF + o] = (int8_t)max(y, 0);
}

// bitlinear + residual-add with int8 wraparound. 64 threads. SRC=0: g_a, SRC=1: g_u
template<int IN, int SRC>
__global__ void linear_res_k(int woff, int l) {
    __shared__ __align__(16) uint32_t xs[IN/4];
    int t = blockIdx.x, o = threadIdx.x;
    const int8_t* in = (SRC == 0) ? g_a : g_u;
    if (o < IN/4) xs[o] = ((const uint32_t*)(in + t*IN))[o];
    __syncthreads();
    const uint32_t* wt = g_wter + l*WPL + woff + o*(IN/4);
    int acc = 0;
    #pragma unroll
    for (int i = 0; i < IN/4; i++) acc = dp4a_ss((int)xs[i], (int)wt[i], acc);
    int y = iclamp(acc >> 6, -128, 127);
    g_x[t*64 + o] = (int8_t)(g_x[t*64 + o] + y);       // wrap-around int8
}

// final rmsnorm -> g_h
__global__ void final_norm_k(const float* __restrict__ fnw) {
    __shared__ __align__(16) uint8_t hs[64];
    __shared__ int red[2];
    int t = blockIdx.x;
    rmsnorm_to_smem(g_x + t*64, fnw, hs, red);
    if (threadIdx.x < 64) g_h[t*64 + threadIdx.x] = (int8_t)hs[threadIdx.x];
}

// ============================================================================
// Attention: 1 warp per query, 8 queries per block, grid (T/8, B*H).
// ============================================================================
__global__ void attn_k() {
    __shared__ int sc[8][1024];                        // scores -> ea
    __shared__ __align__(4) uint8_t pp[8][1024];       // probs u8
    int w = threadIdx.x >> 5, lane = threadIdx.x & 31;
    int bh = blockIdx.y;                               // b*H + h
    int b = bh >> 1, h = bh & 1;
    int qi = blockIdx.x * 8 + w;
    int tq = b*TSEQ + qi;

    const uint32_t* qrow = (const uint32_t*)(g_q + tq*64 + h*32);
    uint32_t qr[8];
    #pragma unroll
    for (int j = 0; j < 8; j++) qr[j] = qrow[j];

    int mymax = -0x7fffffff;
    for (int kb = 0; kb < 32; kb++) {
        int key = kb*32 + lane;
        int s;
        if (key <= qi) {
            const uint32_t* krow = (const uint32_t*)(g_k + (b*TSEQ + key)*64 + h*32);
            int acc = 0;
            #pragma unroll
            for (int j = 0; j < 8; j++) acc = dp4a_ss((int)qr[j], (int)krow[j], acc);
            float f = __fmul_rn(__int2float_rn(acc), 45.0f);
            s = (int)floorf(__fmul_rn(f, 0.00390625f));
        } else {
            s = -32767;
        }
        sc[w][key] = s;
        mymax = max(mymax, s);
    }
    #pragma unroll
    for (int o = 16; o; o >>= 1) mymax = max(mymax, __shfl_xor_sync(0xffffffffu, mymax, o));
    int m = mymax;

    __syncwarp();
    int lsum = 0;
    for (int kb = 0; kb < 32; kb++) {
        int key = kb*32 + lane;
        int sh = sc[w][key] - m;
        int ea;
        if (sh >= -3)       ea = 256 + sh*64;
        else if (sh >= -8)  ea = 64 + (sh + 3)*11;
        else if (sh >= -24) ea = sh + 24;
        else                ea = 0;
        sc[w][key] = ea;
        lsum += ea;
    }
    #pragma unroll
    for (int o = 16; o; o >>= 1) lsum += __shfl_xor_sync(0xffffffffu, lsum, o);
    float fs = (float)max(lsum, 1);

    __syncwarp();
    for (int kb = 0; kb < 32; kb++) {
        int key = kb*32 + lane;
        float p = __fmul_rn(__fdiv_rn((float)sc[w][key], fs), 255.0f);
        pp[w][key] = (uint8_t)iclamp((int)rintf(p), 0, 255);
    }
    __syncwarp();

    const uint32_t* vtd = (const uint32_t*)(g_vt + (bh*32 + lane)*1024);
    const uint32_t* p4 = (const uint32_t*)pp[w];
    int jmax = (qi < 1023 && m <= -32743) ? 256 : ((qi >> 2) + 1);
    int acc = 0;
    for (int j = 0; j < jmax; j++) acc = dp4a_us(p4[j], (int)vtd[j], acc);
    g_a[tq*64 + h*32 + lane] = (int8_t)(acc >> 8);     // floor >>8, then wrap8
}

// ============================================================================
// Logits via IMMA mma.sync m16n8k32.
// CTA = 256 thr (8 warps), tile 128 tokens x 64 vocab.
// Warp w owns tokens tb + w*16 .. +15, loops 8 n-tiles of 8 vocab.
// dot = (s8 x . s8 ehi)*256 + (s8 x . u8 elo), exact int32; out = fl(dot)*2^-13.
// ============================================================================
__global__ void logits_mma_k(float* __restrict__ out) {
    int w = threadIdx.x >> 5, lane = threadIdx.x & 31;
    int g = lane >> 2, t4 = lane & 3;
    int tb = blockIdx.y * 128 + w * 16;
    int nb = blockIdx.x * 64;

    // A fragments: 2 k-steps (K=64) x 4 regs, from g_h rows tb..tb+15
    uint32_t a[2][4];
    const int8_t* xb = g_h + (size_t)tb * 64;
    #pragma unroll
    for (int ks = 0; ks < 2; ks++)
        #pragma unroll
        for (int i = 0; i < 4; i++) {
            int row = g + (i & 1) * 8;
            int k = ks*32 + (i >> 1)*16 + t4*4;
            a[ks][i] = *(const uint32_t*)(xb + row*64 + k);
        }

    #pragma unroll
    for (int nt = 0; nt < 8; nt++) {
        int n0 = nb + nt*8;
        int chi[4] = {0,0,0,0}, clo[4] = {0,0,0,0};
        #pragma unroll
        for (int ks = 0; ks < 2; ks++) {
            uint32_t bh[2], bl[2];
            #pragma unroll
            for (int r = 0; r < 2; r++) {
                int k = ks*32 + r*16 + t4*4;
                bh[r] = *(const uint32_t*)(g_ehi + (size_t)(n0 + g)*64 + k);
                bl[r] = *(const uint32_t*)(g_elo + (size_t)(n0 + g)*64 + k);
            }
            mma_s8s8(chi, a[ks], bh);
            mma_s8u8(clo, a[ks], bl);
        }
        #pragma unroll
        for (int half = 0; half < 2; half++) {
            int row = tb + g + half*8;
            int col = n0 + t4*2;
            float2 val;
            val.x = __fmul_rn(__int2float_rn(chi[half*2+0]*256 + clo[half*2+0]), 1.220703125e-4f);
            val.y = __fmul_rn(__int2float_rn(chi[half*2+1]*256 + clo[half*2+1]), 1.220703125e-4f);
            *(float2*)(out + (size_t)row*VOC + col) = val;
        }
    }
}

// ============================================================================
extern "C" void kernel_launch(void* const* d_in, const int* in_sizes, int n_in,
                              void* d_out, int out_size) {
    const int*   tokens  = (const int*)  d_in[0];
    const float* tok_emb = (const float*)d_in[1];
    const float* pos_emb = (const float*)d_in[2];
    const float* anw     = (const float*)d_in[3];
    const float* qw      = (const float*)d_in[4];
    const float* kw      = (const float*)d_in[5];
    const float* vw      = (const float*)d_in[6];
    const float* ow      = (const float*)d_in[7];
    const float* fnw     = (const float*)d_in[8];
    const float* upw     = (const float*)d_in[9];
    const float* dnw     = (const float*)d_in[10];
    const float* finw    = (const float*)d_in[11];
    float* out = (float*)d_out;

    prep_w_k<<<24, 256>>>(qw, kw, vw, ow, upw, dnw);
    prep_emb_k<<<(VOC*64)/256, 256>>>(tok_emb);
    embed_k<<<(NTOK*64)/256, 256>>>(tokens, tok_emb, pos_emb);

    for (int l = 0; l < 4; l++) {
        norm_qkv_k<<<NTOK, 192>>>(anw, l);
        attn_k<<<dim3(TSEQ/8, 4*NH), 256>>>();
        linear_res_k<64, 0><<<NTOK, 64>>>(3072, l);    // o-proj + residual
        norm_up_k<<<NTOK, 256>>>(fnw, l);
        linear_res_k<256, 1><<<NTOK, 64>>>(8192, l);   // down-proj + residual
    }
    final_norm_k<<<NTOK, 64>>>(finw);
    logits_mma_k<<<dim3(VOC/64, NTOK/128), 256>>>(out);
}

// round 5
// speedup vs baseline: 2.5937x; 2.5239x over previous
#include <cuda_runtime.h>
#include <cstdint>

// ============================================================================
// ZyboGPT hw-accurate quantized transformer forward, bit-exact integer impl.
// B=4 T=1024 D=64 H=2 HD=32 DFF=256 L=4 V=8192
// R4: all GEMMs on IMMA m16n8k32; attention = QK-mma -> gmem scores -> softmax+PV-mma.
// ============================================================================

#define NTOK   4096
#define TSEQ   1024
#define NH     2
#define DFF    256
#define VOC    8192
#define WPL    12288     // u32 words/layer: qkv rows 0..191 @o*16, o@3072, up@4096, down@8192

__device__ __align__(16) int8_t  g_x [NTOK*64];
__device__ __align__(16) int8_t  g_q [NTOK*64];
__device__ __align__(16) int8_t  g_k [NTOK*64];
__device__ __align__(16) int8_t  g_v [NTOK*64];
__device__ __align__(16) int8_t  g_vt[8*32*1024];     // [b*H+h][d][t]
__device__ __align__(16) int8_t  g_a [NTOK*64];
__device__ __align__(16) int8_t  g_u [NTOK*DFF];
__device__ __align__(16) int8_t  g_h [NTOK*64];
__device__ __align__(16) uint32_t g_wter[4*WPL];
__device__ __align__(16) int8_t  g_ehi[VOC*64];
__device__ __align__(16) uint8_t g_elo[VOC*64];
__device__ __align__(16) int     g_sc[8*1024*1024];   // scores [bh][q][k] (lower tiles)

__device__ __forceinline__ int iclamp(int v, int lo, int hi) { return min(max(v, lo), hi); }

// ---- IMMA wrappers: m16n8k32, row.col, s32 accum ----
__device__ __forceinline__ void mma_s8s8(int* c, const uint32_t* a, const uint32_t* b) {
    asm volatile("mma.sync.aligned.m16n8k32.row.col.s32.s8.s8.s32 "
        "{%0,%1,%2,%3}, {%4,%5,%6,%7}, {%8,%9}, {%0,%1,%2,%3};"
        : "+r"(c[0]), "+r"(c[1]), "+r"(c[2]), "+r"(c[3])
        : "r"(a[0]), "r"(a[1]), "r"(a[2]), "r"(a[3]), "r"(b[0]), "r"(b[1]));
}
__device__ __forceinline__ void mma_s8u8(int* c, const uint32_t* a, const uint32_t* b) {
    asm volatile("mma.sync.aligned.m16n8k32.row.col.s32.s8.u8.s32 "
        "{%0,%1,%2,%3}, {%4,%5,%6,%7}, {%8,%9}, {%0,%1,%2,%3};"
        : "+r"(c[0]), "+r"(c[1]), "+r"(c[2]), "+r"(c[3])
        : "r"(a[0]), "r"(a[1]), "r"(a[2]), "r"(a[3]), "r"(b[0]), "r"(b[1]));
}
__device__ __forceinline__ void mma_u8s8(int* c, const uint32_t* a, const uint32_t* b) {
    asm volatile("mma.sync.aligned.m16n8k32.row.col.s32.u8.s8.s32 "
        "{%0,%1,%2,%3}, {%4,%5,%6,%7}, {%8,%9}, {%0,%1,%2,%3};"
        : "+r"(c[0]), "+r"(c[1]), "+r"(c[2]), "+r"(c[3])
        : "r"(a[0]), "r"(a[1]), "r"(a[2]), "r"(a[3]), "r"(b[0]), "r"(b[1]));
}

// ============================================================================
// Weight ternarization
// ============================================================================
__global__ void prep_w_k(const float* __restrict__ qw, const float* __restrict__ kw,
                         const float* __restrict__ vw, const float* __restrict__ ow,
                         const float* __restrict__ upw, const float* __restrict__ dnw) {
    int id = blockIdx.x, l = id / 6, mt = id % 6, tid = threadIdx.x;
    const float* w; int N; uint32_t* dst;
    switch (mt) {
        case 0: w = qw  + l*4096;  N = 4096;  dst = g_wter + l*WPL + 0;    break;
        case 1: w = kw  + l*4096;  N = 4096;  dst = g_wter + l*WPL + 1024; break;
        case 2: w = vw  + l*4096;  N = 4096;  dst = g_wter + l*WPL + 2048; break;
        case 3: w = ow  + l*4096;  N = 4096;  dst = g_wter + l*WPL + 3072; break;
        case 4: w = upw + l*16384; N = 16384; dst = g_wter + l*WPL + 4096; break;
        default:w = dnw + l*16384; N = 16384; dst = g_wter + l*WPL + 8192; break;
    }
    __shared__ float rs[256];
    float s = 0.0f;
    for (int i = tid; i < N; i += 256) s += fabsf(w[i]);
    rs[tid] = s; __syncthreads();
    for (int st = 128; st > 0; st >>= 1) {
        if (tid < st) rs[tid] += rs[tid + st];
        __syncthreads();
    }
    float scale = fmaxf(__fdiv_rn(rs[0], (float)N), 1e-5f);
    for (int wi = tid; wi < N / 4; wi += 256) {
        uint32_t pk = 0;
        #pragma unroll
        for (int j = 0; j < 4; j++) {
            int tv = iclamp((int)rintf(__fdiv_rn(w[wi*4 + j], scale)), -1, 1);
            pk |= ((uint32_t)(tv & 255)) << (8 * j);
        }
        dst[wi] = pk;
    }
}

__global__ void prep_emb_k(const float* __restrict__ temb) {
    int i = blockIdx.x * blockDim.x + threadIdx.x;
    if (i >= VOC * 64) return;
    int q = iclamp((int)rintf(__fmul_rn(temb[i], 1024.0f)), -32768, 32767);
    g_ehi[i] = (int8_t)(q >> 8);
    g_elo[i] = (uint8_t)(q & 255);
}

__global__ void embed_k(const int* __restrict__ tokens, const float* __restrict__ temb,
                        const float* __restrict__ pemb) {
    int i = blockIdx.x * blockDim.x + threadIdx.x;
    if (i >= NTOK * 64) return;
    int t = i >> 6, d = i & 63;
    int tok = tokens[t];
    int tq = iclamp((int)rintf(__fmul_rn(temb[tok*64 + d], 1024.0f)), -32768, 32767);
    int pq = iclamp((int)rintf(__fmul_rn(pemb[(t & 1023)*64 + d], 1024.0f)), -32768, 32767);
    g_x[i] = (int8_t)((tq + pq) >> 3);
}

// ============================================================================
// Tiled norm+linear via IMMA. 64 tokens/block, 256 threads, grid 64.
// MODE: 0 QKV (norm, 64->192)  1 UP (norm+relu, 64->256)
//       2 OPROJ (g_a, 64->64, +res)  3 DOWN (g_u, 256->64, +res)  4 FINALNORM
// ============================================================================
template<int KIN, int NOUT, int MODE>
__global__ void lin_k(const float* __restrict__ nw, int l, int woff) {
    __shared__ __align__(16) int8_t hs[64][80];
    int tid = threadIdx.x, w = tid >> 5, lane = tid & 31, g = lane >> 2, t4 = lane & 3;
    int tbase = blockIdx.x * 64;

    if (MODE == 0 || MODE == 1 || MODE == 4) {
        for (int i = 0; i < 8; i++) {
            int tl = w*8 + i, t = tbase + tl;
            int x0 = g_x[t*64 + lane], x1 = g_x[t*64 + lane + 32];
            int sq = x0*x0 + x1*x1;
            #pragma unroll
            for (int o = 16; o; o >>= 1) sq += __shfl_xor_sync(0xffffffffu, sq, o);
            int lut = min(sq >> 12, 255);
            float bc = (float)(lut*64 + 32);
            int inv = iclamp((int)rintf(__fdiv_rn(16384.0f, __fsqrt_rn(bc))), 0, 16383);
            #pragma unroll
            for (int jj = 0; jj < 2; jj++) {
                int d = lane + jj*32;
                int xi = jj ? x1 : x0;
                int p1 = (xi * inv) >> 8;
                float wc = fminf(fmaxf(nw[d], -2.0f), 2.0f);
                int gq = iclamp((int)rintf(__fmul_rn(wc, 1024.0f)), -32768, 32767);
                float prod = __fmul_rn(__int2float_rn(p1), __int2float_rn(gq));
                int y = (int)floorf(__fmul_rn(prod, 0.0009765625f));
                hs[tl][d] = (int8_t)iclamp(y, -128, 127);
            }
        }
        __syncthreads();
        if (MODE == 4) {
            for (int i = tid; i < 64*16; i += 256) {
                int tl = i >> 4, wd = i & 15;
                ((uint32_t*)(g_h + (size_t)(tbase + tl)*64))[wd] = *(const uint32_t*)&hs[tl][wd*4];
            }
            return;
        }
    }

    constexpr int KS = KIN / 32;
    constexpr int NT = NOUT / 8;
    int mt = w & 3, nh = w >> 2;

    uint32_t a[KS][4];
    #pragma unroll
    for (int ks = 0; ks < KS; ks++)
        #pragma unroll
        for (int i = 0; i < 4; i++) {
            int row = mt*16 + g + (i & 1)*8;
            int k = ks*32 + (i >> 1)*16 + t4*4;
            if (MODE == 0 || MODE == 1)      a[ks][i] = *(const uint32_t*)&hs[row][k];
            else if (MODE == 2)              a[ks][i] = *(const uint32_t*)(g_a + (size_t)(tbase+row)*64 + k);
            else                             a[ks][i] = *(const uint32_t*)(g_u + (size_t)(tbase+row)*256 + k);
        }

    const uint32_t* wb = g_wter + l*WPL + woff;
    for (int nt = nh*(NT/2); nt < (nh+1)*(NT/2); nt++) {
        int n0 = nt*8;
        int c[4] = {0,0,0,0};
        #pragma unroll
        for (int ks = 0; ks < KS; ks++) {
            uint32_t bf[2];
            #pragma unroll
            for (int r = 0; r < 2; r++)
                bf[r] = wb[(n0 + g)*(KIN/4) + ks*8 + r*4 + t4];
            mma_s8s8(c, a[ks], bf);
        }
        #pragma unroll
        for (int idx = 0; idx < 4; idx++) {
            int y = iclamp(c[idx] >> 6, -128, 127);
            int row = tbase + mt*16 + g + (idx >> 1)*8;
            int col = n0 + t4*2 + (idx & 1);
            if (MODE == 0) {
                if (col < 64)       g_q[row*64 + col] = (int8_t)y;
                else if (col < 128) g_k[row*64 + col - 64] = (int8_t)y;
                else {
                    int oo = col - 128;
                    g_v[row*64 + oo] = (int8_t)y;
                    g_vt[((row >> 10)*2 + (oo >> 5))*32768 + (oo & 31)*1024 + (row & 1023)] = (int8_t)y;
                }
            } else if (MODE == 1) {
                g_u[row*256 + col] = (int8_t)max(y, 0);
            } else {
                g_x[row*64 + col] = (int8_t)(g_x[row*64 + col] + y);
            }
        }
    }
}

// ============================================================================
// QK scores via IMMA. grid (16 qt, 8 bh), 256 thr. Writes int32 scores tiles kt<=qt.
// ============================================================================
__global__ void qk_mma_k() {
    int tid = threadIdx.x, w = tid >> 5, lane = tid & 31, g = lane >> 2, t4 = lane & 3;
    int qt = blockIdx.x, bh = blockIdx.y, b = bh >> 1, h = bh & 1;
    int msub = w & 3, khalf = w >> 2;
    int qbase = qt*64 + msub*16;

    uint32_t a[4];
    #pragma unroll
    for (int i = 0; i < 4; i++) {
        int row = qbase + g + (i & 1)*8;
        int k = h*32 + (i >> 1)*16 + t4*4;
        a[i] = *(const uint32_t*)(g_q + (size_t)(b*TSEQ + row)*64 + k);
    }

    for (int kt = 0; kt <= qt; kt++) {
        int kb = kt*64 + khalf*32;
        #pragma unroll
        for (int nt = 0; nt < 4; nt++) {
            int n0 = kb + nt*8;
            int c[4] = {0,0,0,0};
            uint32_t bf[2];
            #pragma unroll
            for (int r = 0; r < 2; r++)
                bf[r] = *(const uint32_t*)(g_k + (size_t)(b*TSEQ + n0 + g)*64 + h*32 + r*16 + t4*4);
            mma_s8s8(c, a, bf);
            #pragma unroll
            for (int half = 0; half < 2; half++) {
                int row = qbase + g + half*8;
                int2 v;
                v.x = (int)floorf(__fmul_rn(__fmul_rn(__int2float_rn(c[half*2+0]), 45.0f), 0.00390625f));
                v.y = (int)floorf(__fmul_rn(__fmul_rn(__int2float_rn(c[half*2+1]), 45.0f), 0.00390625f));
                *(int2*)&g_sc[((size_t)bh*1024 + row)*1024 + n0 + t4*2] = v;
            }
        }
    }
}

// ============================================================================
// softmax (hw PWL) + PV via IMMA. grid (32, 8 bh), 256 thr, 32 queries/block.
// ============================================================================
__global__ void softpv_k() {
    __shared__ __align__(16) uint8_t pp[32][1040];
    int tid = threadIdx.x, w = tid >> 5, lane = tid & 31, g = lane >> 2, t4 = lane & 3;
    int qb = blockIdx.x * 32, bh = blockIdx.y, b = bh >> 1, h = bh & 1;

    // Phase A: per-query softmax, warp w handles 4 queries
    for (int qq = 0; qq < 4; qq++) {
        int q = qb + w*4 + qq, ql = q - qb;
        const int* srow = g_sc + ((size_t)bh*1024 + q)*1024;
        int sreg[32];
        int mymax = -0x7fffffff;
        #pragma unroll
        for (int j = 0; j < 32; j++) {
            int k = j*32 + lane;
            int s = (k <= q) ? srow[k] : -32767;
            sreg[j] = s;
            mymax = max(mymax, s);
        }
        #pragma unroll
        for (int o = 16; o; o >>= 1) mymax = max(mymax, __shfl_xor_sync(0xffffffffu, mymax, o));
        int m = mymax, lsum = 0;
        #pragma unroll
        for (int j = 0; j < 32; j++) {
            int sh = sreg[j] - m;
            int ea;
            if (sh >= -3)       ea = 256 + sh*64;
            else if (sh >= -8)  ea = 64 + (sh + 3)*11;
            else if (sh >= -24) ea = sh + 24;
            else                ea = 0;
            sreg[j] = ea;
            lsum += ea;
        }
        #pragma unroll
        for (int o = 16; o; o >>= 1) lsum += __shfl_xor_sync(0xffffffffu, lsum, o);
        float fs = (float)max(lsum, 1);
        #pragma unroll
        for (int j = 0; j < 32; j++) {
            float p = __fmul_rn(__fdiv_rn((float)sreg[j], fs), 255.0f);
            pp[ql][j*32 + lane] = (uint8_t)iclamp((int)rintf(p), 0, 255);
        }
    }
    __syncthreads();

    // Phase B: PV. warp w: mt = w>>2 (2x16 q), nt = w&3 (4x8 dims)
    int mt = w >> 2, nt = w & 3;
    int c[4] = {0,0,0,0};
    for (int ks = 0; ks < 32; ks++) {
        uint32_t a[4];
        #pragma unroll
        for (int i = 0; i < 4; i++)
            a[i] = *(const uint32_t*)&pp[mt*16 + g + (i & 1)*8][ks*32 + (i >> 1)*16 + t4*4];
        uint32_t bf[2];
        #pragma unroll
        for (int r = 0; r < 2; r++)
            bf[r] = *(const uint32_t*)(g_vt + ((size_t)bh*32 + nt*8 + g)*1024 + ks*32 + r*16 + t4*4);
        mma_u8s8(c, a, bf);
    }
    #pragma unroll
    for (int idx = 0; idx < 4; idx++) {
        int row = qb + mt*16 + g + (idx >> 1)*8;
        int col = nt*8 + t4*2 + (idx & 1);
        g_a[(size_t)(b*TSEQ + row)*64 + h*32 + col] = (int8_t)(c[idx] >> 8);
    }
}

// ============================================================================
// Logits via IMMA (unchanged from R2, validated bit-exact)
// ============================================================================
__global__ void logits_mma_k(float* __restrict__ out) {
    int w = threadIdx.x >> 5, lane = threadIdx.x & 31;
    int g = lane >> 2, t4 = lane & 3;
    int tb = blockIdx.y * 128 + w * 16;
    int nb = blockIdx.x * 64;

    uint32_t a[2][4];
    const int8_t* xb = g_h + (size_t)tb * 64;
    #pragma unroll
    for (int ks = 0; ks < 2; ks++)
        #pragma unroll
        for (int i = 0; i < 4; i++) {
            int row = g + (i & 1) * 8;
            int k = ks*32 + (i >> 1)*16 + t4*4;
            a[ks][i] = *(const uint32_t*)(xb + row*64 + k);
        }

    #pragma unroll
    for (int nt = 0; nt < 8; nt++) {
        int n0 = nb + nt*8;
        int chi[4] = {0,0,0,0}, clo[4] = {0,0,0,0};
        #pragma unroll
        for (int ks = 0; ks < 2; ks++) {
            uint32_t bh[2], bl[2];
            #pragma unroll
            for (int r = 0; r < 2; r++) {
                int k = ks*32 + r*16 + t4*4;
                bh[r] = *(const uint32_t*)(g_ehi + (size_t)(n0 + g)*64 + k);
                bl[r] = *(const uint32_t*)(g_elo + (size_t)(n0 + g)*64 + k);
            }
            mma_s8s8(chi, a[ks], bh);
            mma_s8u8(clo, a[ks], bl);
        }
        #pragma unroll
        for (int half = 0; half < 2; half++) {
            int row = tb + g + half*8;
            int col = n0 + t4*2;
            float2 val;
            val.x = __fmul_rn(__int2float_rn(chi[half*2+0]*256 + clo[half*2+0]), 1.220703125e-4f);
            val.y = __fmul_rn(__int2float_rn(chi[half*2+1]*256 + clo[half*2+1]), 1.220703125e-4f);
            *(float2*)(out + (size_t)row*VOC + col) = val;
        }
    }
}

// ============================================================================
extern "C" void kernel_launch(void* const* d_in, const int* in_sizes, int n_in,
                              void* d_out, int out_size) {
    const int*   tokens  = (const int*)  d_in[0];
    const float* tok_emb = (const float*)d_in[1];
    const float* pos_emb = (const float*)d_in[2];
    const float* anw     = (const float*)d_in[3];
    const float* qw      = (const float*)d_in[4];
    const float* kw      = (const float*)d_in[5];
    const float* vw      = (const float*)d_in[6];
    const float* ow      = (const float*)d_in[7];
    const float* fnw     = (const float*)d_in[8];
    const float* upw     = (const float*)d_in[9];
    const float* dnw     = (const float*)d_in[10];
    const float* finw    = (const float*)d_in[11];
    float* out = (float*)d_out;

    prep_w_k<<<24, 256>>>(qw, kw, vw, ow, upw, dnw);
    prep_emb_k<<<(VOC*64)/256, 256>>>(tok_emb);
    embed_k<<<(NTOK*64)/256, 256>>>(tokens, tok_emb, pos_emb);

    for (int l = 0; l < 4; l++) {
        lin_k<64, 192, 0><<<64, 256>>>(anw + l*64, l, 0);     // norm + QKV
        qk_mma_k<<<dim3(16, 8), 256>>>();
        softpv_k<<<dim3(32, 8), 256>>>();
        lin_k<64, 64, 2><<<64, 256>>>(anw, l, 3072);          // o-proj + residual
        lin_k<64, 256, 1><<<64, 256>>>(fnw + l*64, l, 4096);  // norm + up (relu)
        lin_k<256, 64, 3><<<64, 256>>>(fnw, l, 8192);         // down + residual
    }
    lin_k<64, 8, 4><<<64, 256>>>(finw, 0, 0);                 // final norm -> g_h
    logits_mma_k<<<dim3(VOC/64, NTOK/128), 256>>>(out);
}

// round 7
// speedup vs baseline: 3.7360x; 1.4404x over previous
#include <cuda_runtime.h>
#include <cstdint>

// ============================================================================
// ZyboGPT hw-accurate quantized transformer forward, bit-exact integer impl.
// B=4 T=1024 D=64 H=2 HD=32 DFF=256 L=4 V=8192
// R5: layer-fused token-local megakernel (oproj+up+down+next-qkv),
//     balanced triangular QK grid, causal-bounded PV. 16 launches total.
// ============================================================================

#define NTOK   4096
#define TSEQ   1024
#define NH     2
#define DFF    256
#define VOC    8192
#define WPL    12288     // u32 words/layer: qkv@0, o@3072, up@4096, down@8192

__device__ __align__(16) int8_t  g_x [NTOK*64];
__device__ __align__(16) int8_t  g_q [NTOK*64];
__device__ __align__(16) int8_t  g_k [NTOK*64];
__device__ __align__(16) int8_t  g_v [NTOK*64];
__device__ __align__(16) int8_t  g_vt[8*32*1024];     // [b*H+h][d][t]
__device__ __align__(16) int8_t  g_a [NTOK*64];
__device__ __align__(16) int8_t  g_u [NTOK*DFF];
__device__ __align__(16) int8_t  g_h [NTOK*64];
__device__ __align__(16) uint32_t g_wter[4*WPL];
__device__ __align__(16) int8_t  g_ehi[VOC*64];
__device__ __align__(16) uint8_t g_elo[VOC*64];
__device__ __align__(16) int     g_sc[8*1024*1024];   // scores [bh][q][k] (lower tiles)

__device__ __forceinline__ int iclamp(int v, int lo, int hi) { return min(max(v, lo), hi); }

// ---- IMMA wrappers: m16n8k32, row.col, s32 accum ----
__device__ __forceinline__ void mma_s8s8(int* c, const uint32_t* a, const uint32_t* b) {
    asm volatile("mma.sync.aligned.m16n8k32.row.col.s32.s8.s8.s32 "
        "{%0,%1,%2,%3}, {%4,%5,%6,%7}, {%8,%9}, {%0,%1,%2,%3};"
        : "+r"(c[0]), "+r"(c[1]), "+r"(c[2]), "+r"(c[3])
        : "r"(a[0]), "r"(a[1]), "r"(a[2]), "r"(a[3]), "r"(b[0]), "r"(b[1]));
}
__device__ __forceinline__ void mma_s8u8(int* c, const uint32_t* a, const uint32_t* b) {
    asm volatile("mma.sync.aligned.m16n8k32.row.col.s32.s8.u8.s32 "
        "{%0,%1,%2,%3}, {%4,%5,%6,%7}, {%8,%9}, {%0,%1,%2,%3};"
        : "+r"(c[0]), "+r"(c[1]), "+r"(c[2]), "+r"(c[3])
        : "r"(a[0]), "r"(a[1]), "r"(a[2]), "r"(a[3]), "r"(b[0]), "r"(b[1]));
}
__device__ __forceinline__ void mma_u8s8(int* c, const uint32_t* a, const uint32_t* b) {
    asm volatile("mma.sync.aligned.m16n8k32.row.col.s32.u8.s8.s32 "
        "{%0,%1,%2,%3}, {%4,%5,%6,%7}, {%8,%9}, {%0,%1,%2,%3};"
        : "+r"(c[0]), "+r"(c[1]), "+r"(c[2]), "+r"(c[3])
        : "r"(a[0]), "r"(a[1]), "r"(a[2]), "r"(a[3]), "r"(b[0]), "r"(b[1]));
}

// A-fragment loader (16 rows x KIN cols), src row-major with stride ldm bytes.
template<int KIN>
__device__ __forceinline__ void load_a(uint32_t a[][4], const int8_t* src, int ldm,
                                       int mt, int g, int t4) {
    #pragma unroll
    for (int ks = 0; ks < KIN/32; ks++)
        #pragma unroll
        for (int i = 0; i < 4; i++) {
            int row = mt*16 + g + (i & 1)*8;
            int k = ks*32 + (i >> 1)*16 + t4*4;
            a[ks][i] = *(const uint32_t*)(src + (size_t)row*ldm + k);
        }
}

// MMA vs ternary weight tile (8 out cols starting n0)
template<int KIN>
__device__ __forceinline__ void mma_w(int c[4], const uint32_t a[][4],
                                      const uint32_t* wb, int n0, int g, int t4) {
    #pragma unroll
    for (int ks = 0; ks < KIN/32; ks++) {
        uint32_t bf[2];
        #pragma unroll
        for (int r = 0; r < 2; r++)
            bf[r] = wb[(n0 + g)*(KIN/4) + ks*8 + r*4 + t4];
        mma_s8s8(c, a[ks], bf);
    }
}

// ============================================================================
// rmsnorm of 32 tokens (tbase..) into hs[32][80]. 8 warps x 4 tokens.
// ============================================================================
__device__ __forceinline__ void norm32(int tbase, const float* __restrict__ nw,
                                       int8_t hs[32][80], int w, int lane) {
    #pragma unroll
    for (int i = 0; i < 4; i++) {
        int tl = w*4 + i, t = tbase + tl;
        int x0 = g_x[t*64 + lane], x1 = g_x[t*64 + lane + 32];
        int sq = x0*x0 + x1*x1;
        #pragma unroll
        for (int o = 16; o; o >>= 1) sq += __shfl_xor_sync(0xffffffffu, sq, o);
        int lut = min(sq >> 12, 255);
        float bc = (float)(lut*64 + 32);
        int inv = iclamp((int)rintf(__fdiv_rn(16384.0f, __fsqrt_rn(bc))), 0, 16383);
        #pragma unroll
        for (int jj = 0; jj < 2; jj++) {
            int d = lane + jj*32;
            int xi = jj ? x1 : x0;
            int p1 = (xi * inv) >> 8;
            float wc = fminf(fmaxf(nw[d], -2.0f), 2.0f);
            int gq = iclamp((int)rintf(__fmul_rn(wc, 1024.0f)), -32768, 32767);
            float prod = __fmul_rn(__int2float_rn(p1), __int2float_rn(gq));
            int y = (int)floorf(__fmul_rn(prod, 0.0009765625f));
            hs[tl][d] = (int8_t)iclamp(y, -128, 127);
        }
    }
}

// QKV projection from hs -> g_q/g_k/g_v/g_vt. warp: mt=w&1, nh=w>>1 (6 ntiles).
__device__ __forceinline__ void qkv_mma(int tbase, const uint32_t* wl,
                                        int8_t hs[32][80], int w, int lane) {
    int g = lane >> 2, t4 = lane & 3, mt = w & 1, nh = w >> 1;
    uint32_t a[2][4];
    load_a<64>(a, &hs[0][0], 80, mt, g, t4);
    for (int nt = nh*6; nt < nh*6 + 6; nt++) {
        int n0 = nt*8;
        int c[4] = {0,0,0,0};
        mma_w<64>(c, a, wl, n0, g, t4);
        #pragma unroll
        for (int idx = 0; idx < 4; idx++) {
            int y = iclamp(c[idx] >> 6, -128, 127);
            int row = tbase + mt*16 + g + (idx >> 1)*8;
            int col = n0 + t4*2 + (idx & 1);
            if (col < 64)       g_q[row*64 + col] = (int8_t)y;
            else if (col < 128) g_k[row*64 + col - 64] = (int8_t)y;
            else {
                int oo = col - 128;
                g_v[row*64 + oo] = (int8_t)y;
                g_vt[((row >> 10)*2 + (oo >> 5))*32768 + (oo & 31)*1024 + (row & 1023)] = (int8_t)y;
            }
        }
    }
}

// ============================================================================
// Weight ternarization + embedding prep (unchanged numerics)
// ============================================================================
__global__ void prep_w_k(const float* __restrict__ qw, const float* __restrict__ kw,
                         const float* __restrict__ vw, const float* __restrict__ ow,
                         const float* __restrict__ upw, const float* __restrict__ dnw) {
    int id = blockIdx.x, l = id / 6, mt = id % 6, tid = threadIdx.x;
    const float* w; int N; uint32_t* dst;
    switch (mt) {
        case 0: w = qw  + l*4096;  N = 4096;  dst = g_wter + l*WPL + 0;    break;
        case 1: w = kw  + l*4096;  N = 4096;  dst = g_wter + l*WPL + 1024; break;
        case 2: w = vw  + l*4096;  N = 4096;  dst = g_wter + l*WPL + 2048; break;
        case 3: w = ow  + l*4096;  N = 4096;  dst = g_wter + l*WPL + 3072; break;
        case 4: w = upw + l*16384; N = 16384; dst = g_wter + l*WPL + 4096; break;
        default:w = dnw + l*16384; N = 16384; dst = g_wter + l*WPL + 8192; break;
    }
    __shared__ float rs[256];
    float s = 0.0f;
    for (int i = tid; i < N; i += 256) s += fabsf(w[i]);
    rs[tid] = s; __syncthreads();
    for (int st = 128; st > 0; st >>= 1) {
        if (tid < st) rs[tid] += rs[tid + st];
        __syncthreads();
    }
    float scale = fmaxf(__fdiv_rn(rs[0], (float)N), 1e-5f);
    for (int wi = tid; wi < N / 4; wi += 256) {
        uint32_t pk = 0;
        #pragma unroll
        for (int j = 0; j < 4; j++) {
            int tv = iclamp((int)rintf(__fdiv_rn(w[wi*4 + j], scale)), -1, 1);
            pk |= ((uint32_t)(tv & 255)) << (8 * j);
        }
        dst[wi] = pk;
    }
}

__global__ void prep_emb_k(const float* __restrict__ temb) {
    int i = blockIdx.x * blockDim.x + threadIdx.x;
    if (i >= VOC * 64) return;
    int q = iclamp((int)rintf(__fmul_rn(temb[i], 1024.0f)), -32768, 32767);
    g_ehi[i] = (int8_t)(q >> 8);
    g_elo[i] = (uint8_t)(q & 255);
}

// ============================================================================
// Fused: embed 32 tokens + norm + QKV(l=0). grid 128, 256 thr.
// ============================================================================
__global__ void emb_qkv0_k(const int* __restrict__ tokens, const float* __restrict__ temb,
                           const float* __restrict__ pemb, const float* __restrict__ anw) {
    __shared__ __align__(16) int8_t hs[32][80];
    int tid = threadIdx.x, w = tid >> 5, lane = tid & 31;
    int tbase = blockIdx.x * 32;
    for (int i = tid; i < 32*64; i += 256) {
        int tl = i >> 6, d = i & 63, t = tbase + tl;
        int tok = tokens[t];
        int tq = iclamp((int)rintf(__fmul_rn(temb[tok*64 + d], 1024.0f)), -32768, 32767);
        int pq = iclamp((int)rintf(__fmul_rn(pemb[(t & 1023)*64 + d], 1024.0f)), -32768, 32767);
        g_x[t*64 + d] = (int8_t)((tq + pq) >> 3);
    }
    __syncthreads();
    norm32(tbase, anw, hs, w, lane);
    __syncthreads();
    qkv_mma(tbase, g_wter, hs, w, lane);
}

// ============================================================================
// QK scores, balanced triangular grid: blockIdx.x in [0,136) -> (qt,kt) with kt<=qt.
// Each block: one 64x64 tile. grid (136, 8).
// ============================================================================
__global__ void qk_mma_k() {
    int tid = threadIdx.x, w = tid >> 5, lane = tid & 31, g = lane >> 2, t4 = lane & 3;
    int idx = blockIdx.x, bh = blockIdx.y, b = bh >> 1, h = bh & 1;
    int qt = (int)((sqrtf(8.0f*idx + 1.0f) - 1.0f) * 0.5f);
    while ((qt + 1)*(qt + 2)/2 <= idx) qt++;
    while (qt*(qt + 1)/2 > idx) qt--;
    int kt = idx - qt*(qt + 1)/2;

    int msub = w & 3, khalf = w >> 2;
    int qbase = qt*64 + msub*16;
    uint32_t a[4];
    #pragma unroll
    for (int i = 0; i < 4; i++) {
        int row = qbase + g + (i & 1)*8;
        int k = h*32 + (i >> 1)*16 + t4*4;
        a[i] = *(const uint32_t*)(g_q + (size_t)(b*TSEQ + row)*64 + k);
    }
    int kb = kt*64 + khalf*32;
    #pragma unroll
    for (int nt = 0; nt < 4; nt++) {
        int n0 = kb + nt*8;
        int c[4] = {0,0,0,0};
        uint32_t bf[2];
        #pragma unroll
        for (int r = 0; r < 2; r++)
            bf[r] = *(const uint32_t*)(g_k + (size_t)(b*TSEQ + n0 + g)*64 + h*32 + r*16 + t4*4);
        mma_s8s8(c, a, bf);
        #pragma unroll
        for (int half = 0; half < 2; half++) {
            int row = qbase + g + half*8;
            int2 v;
            v.x = (int)floorf(__fmul_rn(__fmul_rn(__int2float_rn(c[half*2+0]), 45.0f), 0.00390625f));
            v.y = (int)floorf(__fmul_rn(__fmul_rn(__int2float_rn(c[half*2+1]), 45.0f), 0.00390625f));
            *(int2*)&g_sc[((size_t)bh*1024 + row)*1024 + n0 + t4*2] = v;
        }
    }
}

// ============================================================================
// softmax (hw PWL) + PV via IMMA, causal-bounded. grid (32, 8), 256 thr.
// ============================================================================
__global__ void softpv_k() {
    __shared__ __align__(16) uint8_t pp[32][1040];
    __shared__ int fullflag;
    int tid = threadIdx.x, w = tid >> 5, lane = tid & 31, g = lane >> 2, t4 = lane & 3;
    int qb = blockIdx.x * 32, bh = blockIdx.y, b = bh >> 1, h = bh & 1;
    if (tid == 0) fullflag = 0;
    __syncthreads();

    int anyfull = 0;
    for (int qq = 0; qq < 4; qq++) {
        int q = qb + w*4 + qq, ql = q - qb;
        const int* srow = g_sc + ((size_t)bh*1024 + q)*1024;
        int sreg[32];
        int mymax = -0x7fffffff;
        #pragma unroll
        for (int j = 0; j < 32; j++) {
            int k = j*32 + lane;
            int s = (k <= q) ? srow[k] : -32767;
            sreg[j] = s;
            mymax = max(mymax, s);
        }
        #pragma unroll
        for (int o = 16; o; o >>= 1) mymax = max(mymax, __shfl_xor_sync(0xffffffffu, mymax, o));
        int m = mymax, lsum = 0;
        if (m <= -32743) anyfull = 1;      // masked keys contribute in this regime
        #pragma unroll
        for (int j = 0; j < 32; j++) {
            int sh = sreg[j] - m;
            int ea;
            if (sh >= -3)       ea = 256 + sh*64;
            else if (sh >= -8)  ea = 64 + (sh + 3)*11;
            else if (sh >= -24) ea = sh + 24;
            else                ea = 0;
            sreg[j] = ea;
            lsum += ea;
        }
        #pragma unroll
        for (int o = 16; o; o >>= 1) lsum += __shfl_xor_sync(0xffffffffu, lsum, o);
        float fs = (float)max(lsum, 1);
        #pragma unroll
        for (int j = 0; j < 32; j++) {
            float p = __fmul_rn(__fdiv_rn((float)sreg[j], fs), 255.0f);
            pp[ql][j*32 + lane] = (uint8_t)iclamp((int)rintf(p), 0, 255);
        }
    }
    if (anyfull) atomicOr(&fullflag, 1);
    __syncthreads();

    int nkb = fullflag ? 32 : (qb >> 5) + 1;
    int mt = w >> 2, nt = w & 3;
    int c[4] = {0,0,0,0};
    for (int ks = 0; ks < nkb; ks++) {
        uint32_t a[4];
        #pragma unroll
        for (int i = 0; i < 4; i++)
            a[i] = *(const uint32_t*)&pp[mt*16 + g + (i & 1)*8][ks*32 + (i >> 1)*16 + t4*4];
        uint32_t bf[2];
        #pragma unroll
        for (int r = 0; r < 2; r++)
            bf[r] = *(const uint32_t*)(g_vt + ((size_t)bh*32 + nt*8 + g)*1024 + ks*32 + r*16 + t4*4);
        mma_u8s8(c, a, bf);
    }
    #pragma unroll
    for (int idx = 0; idx < 4; idx++) {
        int row = qb + mt*16 + g + (idx >> 1)*8;
        int col = nt*8 + t4*2 + (idx & 1);
        g_a[(size_t)(b*TSEQ + row)*64 + h*32 + col] = (int8_t)(c[idx] >> 8);
    }
}

// ============================================================================
// Layer-fused FFN megakernel: oproj+res -> norm -> up(relu) -> down+res ->
// (next-layer norm+QKV | final norm -> g_h). 32 tokens/block, grid 128.
// ============================================================================
template<bool LAST>
__global__ void ffn_k(const float* __restrict__ anw, const float* __restrict__ fnw,
                      const float* __restrict__ finw, int l) {
    __shared__ __align__(16) int8_t hs[32][80];
    int tid = threadIdx.x, w = tid >> 5, lane = tid & 31, g = lane >> 2, t4 = lane & 3;
    int mt = w & 1, nh = w >> 1;
    int tbase = blockIdx.x * 32;
    const uint32_t* wl = g_wter + l*WPL;

    // ---- o-proj + residual ----
    {
        uint32_t a[2][4];
        load_a<64>(a, g_a + (size_t)tbase*64, 64, mt, g, t4);
        for (int nt = nh*2; nt < nh*2 + 2; nt++) {
            int n0 = nt*8;
            int c[4] = {0,0,0,0};
            mma_w<64>(c, a, wl + 3072, n0, g, t4);
            #pragma unroll
            for (int idx = 0; idx < 4; idx++) {
                int y = iclamp(c[idx] >> 6, -128, 127);
                int row = tbase + mt*16 + g + (idx >> 1)*8;
                int col = n0 + t4*2 + (idx & 1);
                g_x[row*64 + col] = (int8_t)(g_x[row*64 + col] + y);
            }
        }
    }
    __syncthreads();
    // ---- ffn norm ----
    norm32(tbase, fnw + l*64, hs, w, lane);
    __syncthreads();
    // ---- up-proj + relu ----
    {
        uint32_t a[2][4];
        load_a<64>(a, &hs[0][0], 80, mt, g, t4);
        for (int nt = nh*8; nt < nh*8 + 8; nt++) {
            int n0 = nt*8;
            int c[4] = {0,0,0,0};
            mma_w<64>(c, a, wl + 4096, n0, g, t4);
            #pragma unroll
            for (int idx = 0; idx < 4; idx++) {
                int y = iclamp(c[idx] >> 6, -128, 127);
                int row = tbase + mt*16 + g + (idx >> 1)*8;
                int col = n0 + t4*2 + (idx & 1);
                g_u[row*256 + col] = (int8_t)max(y, 0);
            }
        }
    }
    __syncthreads();
    // ---- down-proj + residual ----
    {
        uint32_t a[8][4];
        load_a<256>(a, g_u + (size_t)tbase*256, 256, mt, g, t4);
        for (int nt = nh*2; nt < nh*2 + 2; nt++) {
            int n0 = nt*8;
            int c[4] = {0,0,0,0};
            mma_w<256>(c, a, wl + 8192, n0, g, t4);
            #pragma unroll
            for (int idx = 0; idx < 4; idx++) {
                int y = iclamp(c[idx] >> 6, -128, 127);
                int row = tbase + mt*16 + g + (idx >> 1)*8;
                int col = n0 + t4*2 + (idx & 1);
                g_x[row*64 + col] = (int8_t)(g_x[row*64 + col] + y);
            }
        }
    }
    __syncthreads();
    // ---- next norm (+QKV) or final norm ----
    if (LAST) {
        norm32(tbase, finw, hs, w, lane);
        __syncthreads();
        for (int i = tid; i < 32*16; i += 256) {
            int tl = i >> 4, wd = i & 15;
            ((uint32_t*)(g_h + (size_t)(tbase + tl)*64))[wd] = *(const uint32_t*)&hs[tl][wd*4];
        }
    } else {
        norm32(tbase, anw + (l+1)*64, hs, w, lane);
        __syncthreads();
        qkv_mma(tbase, g_wter + (l+1)*WPL, hs, w, lane);
    }
}

// ============================================================================
// Logits via IMMA (validated bit-exact)
// ============================================================================
__global__ void logits_mma_k(float* __restrict__ out) {
    int w = threadIdx.x >> 5, lane = threadIdx.x & 31;
    int g = lane >> 2, t4 = lane & 3;
    int tb = blockIdx.y * 128 + w * 16;
    int nb = blockIdx.x * 64;

    uint32_t a[2][4];
    const int8_t* xb = g_h + (size_t)tb * 64;
    #pragma unroll
    for (int ks = 0; ks < 2; ks++)
        #pragma unroll
        for (int i = 0; i < 4; i++) {
            int row = g + (i & 1) * 8;
            int k = ks*32 + (i >> 1)*16 + t4*4;
            a[ks][i] = *(const uint32_t*)(xb + row*64 + k);
        }

    #pragma unroll
    for (int nt = 0; nt < 8; nt++) {
        int n0 = nb + nt*8;
        int chi[4] = {0,0,0,0}, clo[4] = {0,0,0,0};
        #pragma unroll
        for (int ks = 0; ks < 2; ks++) {
            uint32_t bh[2], bl[2];
            #pragma unroll
            for (int r = 0; r < 2; r++) {
                int k = ks*32 + r*16 + t4*4;
                bh[r] = *(const uint32_t*)(g_ehi + (size_t)(n0 + g)*64 + k);
                bl[r] = *(const uint32_t*)(g_elo + (size_t)(n0 + g)*64 + k);
            }
            mma_s8s8(chi, a[ks], bh);
            mma_s8u8(clo, a[ks], bl);
        }
        #pragma unroll
        for (int half = 0; half < 2; half++) {
            int row = tb + g + half*8;
            int col = n0 + t4*2;
            float2 val;
            val.x = __fmul_rn(__int2float_rn(chi[half*2+0]*256 + clo[half*2+0]), 1.220703125e-4f);
            val.y = __fmul_rn(__int2float_rn(chi[half*2+1]*256 + clo[half*2+1]), 1.220703125e-4f);
            *(float2*)(out + (size_t)row*VOC + col) = val;
        }
    }
}

// ============================================================================
extern "C" void kernel_launch(void* const* d_in, const int* in_sizes, int n_in,
                              void* d_out, int out_size) {
    const int*   tokens  = (const int*)  d_in[0];
    const float* tok_emb = (const float*)d_in[1];
    const float* pos_emb = (const float*)d_in[2];
    const float* anw     = (const float*)d_in[3];
    const float* qw      = (const float*)d_in[4];
    const float* kw      = (const float*)d_in[5];
    const float* vw      = (const float*)d_in[6];
    const float* ow      = (const float*)d_in[7];
    const float* fnw     = (const float*)d_in[8];
    const float* upw     = (const float*)d_in[9];
    const float* dnw     = (const float*)d_in[10];
    const float* finw    = (const float*)d_in[11];
    float* out = (float*)d_out;

    prep_w_k<<<24, 256>>>(qw, kw, vw, ow, upw, dnw);
    prep_emb_k<<<(VOC*64)/256, 256>>>(tok_emb);
    emb_qkv0_k<<<128, 256>>>(tokens, tok_emb, pos_emb, anw);

    for (int l = 0; l < 4; l++) {
        qk_mma_k<<<dim3(136, 8), 256>>>();
        softpv_k<<<dim3(32, 8), 256>>>();
        if (l < 3) ffn_k<false><<<128, 256>>>(anw, fnw, finw, l);
        else       ffn_k<true ><<<128, 256>>>(anw, fnw, finw, l);
    }
    logits_mma_k<<<dim3(VOC/64, NTOK/128), 256>>>(out);
}

// round 8
// speedup vs baseline: 3.8544x; 1.0317x over previous
#include <cuda_runtime.h>
#include <cstdint>

// ============================================================================
// ZyboGPT hw-accurate quantized transformer forward, bit-exact integer impl.
// B=4 T=1024 D=64 H=2 HD=32 DFF=256 L=4 V=8192
// R7: single fused attention kernel per layer (QK -> hw softmax -> PV in smem),
//     no score gmem round-trip. 12 launches total.
// ============================================================================

#define NTOK   4096
#define TSEQ   1024
#define NH     2
#define DFF    256
#define VOC    8192
#define WPL    12288     // u32 words/layer: qkv@0, o@3072, up@4096, down@8192

#define SC_STR 1032      // score smem row stride (ints)
#define PP_STR 1056      // prob smem row stride (bytes)
#define SMEM_ATT (16*SC_STR*4 + 16*PP_STR + 4*32*4*4 + 16)

__device__ __align__(16) int8_t  g_x [NTOK*64];
__device__ __align__(16) int8_t  g_q [NTOK*64];
__device__ __align__(16) int8_t  g_k [NTOK*64];
__device__ __align__(16) int8_t  g_v [NTOK*64];
__device__ __align__(16) int8_t  g_vt[8*32*1024];     // [b*H+h][d][t]
__device__ __align__(16) int8_t  g_a [NTOK*64];
__device__ __align__(16) int8_t  g_u [NTOK*DFF];
__device__ __align__(16) int8_t  g_h [NTOK*64];
__device__ __align__(16) uint32_t g_wter[4*WPL];
__device__ __align__(16) int8_t  g_ehi[VOC*64];
__device__ __align__(16) uint8_t g_elo[VOC*64];

__device__ __forceinline__ int iclamp(int v, int lo, int hi) { return min(max(v, lo), hi); }

// ---- IMMA wrappers: m16n8k32, row.col, s32 accum ----
__device__ __forceinline__ void mma_s8s8(int* c, const uint32_t* a, const uint32_t* b) {
    asm volatile("mma.sync.aligned.m16n8k32.row.col.s32.s8.s8.s32 "
        "{%0,%1,%2,%3}, {%4,%5,%6,%7}, {%8,%9}, {%0,%1,%2,%3};"
        : "+r"(c[0]), "+r"(c[1]), "+r"(c[2]), "+r"(c[3])
        : "r"(a[0]), "r"(a[1]), "r"(a[2]), "r"(a[3]), "r"(b[0]), "r"(b[1]));
}
__device__ __forceinline__ void mma_s8u8(int* c, const uint32_t* a, const uint32_t* b) {
    asm volatile("mma.sync.aligned.m16n8k32.row.col.s32.s8.u8.s32 "
        "{%0,%1,%2,%3}, {%4,%5,%6,%7}, {%8,%9}, {%0,%1,%2,%3};"
        : "+r"(c[0]), "+r"(c[1]), "+r"(c[2]), "+r"(c[3])
        : "r"(a[0]), "r"(a[1]), "r"(a[2]), "r"(a[3]), "r"(b[0]), "r"(b[1]));
}
__device__ __forceinline__ void mma_u8s8(int* c, const uint32_t* a, const uint32_t* b) {
    asm volatile("mma.sync.aligned.m16n8k32.row.col.s32.u8.s8.s32 "
        "{%0,%1,%2,%3}, {%4,%5,%6,%7}, {%8,%9}, {%0,%1,%2,%3};"
        : "+r"(c[0]), "+r"(c[1]), "+r"(c[2]), "+r"(c[3])
        : "r"(a[0]), "r"(a[1]), "r"(a[2]), "r"(a[3]), "r"(b[0]), "r"(b[1]));
}

template<int KIN>
__device__ __forceinline__ void load_a(uint32_t a[][4], const int8_t* src, int ldm,
                                       int mt, int g, int t4) {
    #pragma unroll
    for (int ks = 0; ks < KIN/32; ks++)
        #pragma unroll
        for (int i = 0; i < 4; i++) {
            int row = mt*16 + g + (i & 1)*8;
            int k = ks*32 + (i >> 1)*16 + t4*4;
            a[ks][i] = *(const uint32_t*)(src + (size_t)row*ldm + k);
        }
}

template<int KIN>
__device__ __forceinline__ void mma_w(int c[4], const uint32_t a[][4],
                                      const uint32_t* wb, int n0, int g, int t4) {
    #pragma unroll
    for (int ks = 0; ks < KIN/32; ks++) {
        uint32_t bf[2];
        #pragma unroll
        for (int r = 0; r < 2; r++)
            bf[r] = wb[(n0 + g)*(KIN/4) + ks*8 + r*4 + t4];
        mma_s8s8(c, a[ks], bf);
    }
}

// ============================================================================
// rmsnorm of 32 tokens into hs[32][80]. 8 warps x 4 tokens.
// ============================================================================
__device__ __forceinline__ void norm32(int tbase, const float* __restrict__ nw,
                                       int8_t hs[32][80], int w, int lane) {
    #pragma unroll
    for (int i = 0; i < 4; i++) {
        int tl = w*4 + i, t = tbase + tl;
        int x0 = g_x[t*64 + lane], x1 = g_x[t*64 + lane + 32];
        int sq = x0*x0 + x1*x1;
        #pragma unroll
        for (int o = 16; o; o >>= 1) sq += __shfl_xor_sync(0xffffffffu, sq, o);
        int lut = min(sq >> 12, 255);
        float bc = (float)(lut*64 + 32);
        int inv = iclamp((int)rintf(__fdiv_rn(16384.0f, __fsqrt_rn(bc))), 0, 16383);
        #pragma unroll
        for (int jj = 0; jj < 2; jj++) {
            int d = lane + jj*32;
            int xi = jj ? x1 : x0;
            int p1 = (xi * inv) >> 8;
            float wc = fminf(fmaxf(nw[d], -2.0f), 2.0f);
            int gq = iclamp((int)rintf(__fmul_rn(wc, 1024.0f)), -32768, 32767);
            float prod = __fmul_rn(__int2float_rn(p1), __int2float_rn(gq));
            int y = (int)floorf(__fmul_rn(prod, 0.0009765625f));
            hs[tl][d] = (int8_t)iclamp(y, -128, 127);
        }
    }
}

__device__ __forceinline__ void qkv_mma(int tbase, const uint32_t* wl,
                                        int8_t hs[32][80], int w, int lane) {
    int g = lane >> 2, t4 = lane & 3, mt = w & 1, nh = w >> 1;
    uint32_t a[2][4];
    load_a<64>(a, &hs[0][0], 80, mt, g, t4);
    for (int nt = nh*6; nt < nh*6 + 6; nt++) {
        int n0 = nt*8;
        int c[4] = {0,0,0,0};
        mma_w<64>(c, a, wl, n0, g, t4);
        #pragma unroll
        for (int idx = 0; idx < 4; idx++) {
            int y = iclamp(c[idx] >> 6, -128, 127);
            int row = tbase + mt*16 + g + (idx >> 1)*8;
            int col = n0 + t4*2 + (idx & 1);
            if (col < 64)       g_q[row*64 + col] = (int8_t)y;
            else if (col < 128) g_k[row*64 + col - 64] = (int8_t)y;
            else {
                int oo = col - 128;
                g_v[row*64 + oo] = (int8_t)y;
                g_vt[((row >> 10)*2 + (oo >> 5))*32768 + (oo & 31)*1024 + (row & 1023)] = (int8_t)y;
            }
        }
    }
}

// ============================================================================
// Prep kernels (unchanged numerics)
// ============================================================================
__global__ void prep_w_k(const float* __restrict__ qw, const float* __restrict__ kw,
                         const float* __restrict__ vw, const float* __restrict__ ow,
                         const float* __restrict__ upw, const float* __restrict__ dnw) {
    int id = blockIdx.x, l = id / 6, mt = id % 6, tid = threadIdx.x;
    const float* w; int N; uint32_t* dst;
    switch (mt) {
        case 0: w = qw  + l*4096;  N = 4096;  dst = g_wter + l*WPL + 0;    break;
        case 1: w = kw  + l*4096;  N = 4096;  dst = g_wter + l*WPL + 1024; break;
        case 2: w = vw  + l*4096;  N = 4096;  dst = g_wter + l*WPL + 2048; break;
        case 3: w = ow  + l*4096;  N = 4096;  dst = g_wter + l*WPL + 3072; break;
        case 4: w = upw + l*16384; N = 16384; dst = g_wter + l*WPL + 4096; break;
        default:w = dnw + l*16384; N = 16384; dst = g_wter + l*WPL + 8192; break;
    }
    __shared__ float rs[256];
    float s = 0.0f;
    for (int i = tid; i < N; i += 256) s += fabsf(w[i]);
    rs[tid] = s; __syncthreads();
    for (int st = 128; st > 0; st >>= 1) {
        if (tid < st) rs[tid] += rs[tid + st];
        __syncthreads();
    }
    float scale = fmaxf(__fdiv_rn(rs[0], (float)N), 1e-5f);
    for (int wi = tid; wi < N / 4; wi += 256) {
        uint32_t pk = 0;
        #pragma unroll
        for (int j = 0; j < 4; j++) {
            int tv = iclamp((int)rintf(__fdiv_rn(w[wi*4 + j], scale)), -1, 1);
            pk |= ((uint32_t)(tv & 255)) << (8 * j);
        }
        dst[wi] = pk;
    }
}

__global__ void prep_emb_k(const float* __restrict__ temb) {
    int i = blockIdx.x * blockDim.x + threadIdx.x;
    if (i >= VOC * 64) return;
    int q = iclamp((int)rintf(__fmul_rn(temb[i], 1024.0f)), -32768, 32767);
    g_ehi[i] = (int8_t)(q >> 8);
    g_elo[i] = (uint8_t)(q & 255);
}

__global__ void emb_qkv0_k(const int* __restrict__ tokens, const float* __restrict__ temb,
                           const float* __restrict__ pemb, const float* __restrict__ anw) {
    __shared__ __align__(16) int8_t hs[32][80];
    int tid = threadIdx.x, w = tid >> 5, lane = tid & 31;
    int tbase = blockIdx.x * 32;
    for (int i = tid; i < 32*64; i += 256) {
        int tl = i >> 6, d = i & 63, t = tbase + tl;
        int tok = tokens[t];
        int tq = iclamp((int)rintf(__fmul_rn(temb[tok*64 + d], 1024.0f)), -32768, 32767);
        int pq = iclamp((int)rintf(__fmul_rn(pemb[(t & 1023)*64 + d], 1024.0f)), -32768, 32767);
        g_x[t*64 + d] = (int8_t)((tq + pq) >> 3);
    }
    __syncthreads();
    norm32(tbase, anw, hs, w, lane);
    __syncthreads();
    qkv_mma(tbase, g_wter, hs, w, lane);
}

// ============================================================================
// Fused attention: QK -> hw softmax -> PV, all in one block per (bh, 16 q-rows).
// grid (64 reversed, 8 bh), 256 thr, ~85KB dynamic smem.
// ============================================================================
__global__ __launch_bounds__(256) void attn_fused_k() {
    extern __shared__ int sm[];
    int*     sc   = sm;                                 // [16][SC_STR] scores
    uint8_t* pp   = (uint8_t*)(sc + 16*SC_STR);         // [16][PP_STR] probs
    int*     red  = (int*)(pp + 16*PP_STR);             // [4][32][4] PV partials
    int*     flagp = red + 4*32*4;

    int tid = threadIdx.x, w = tid >> 5, lane = tid & 31, g = lane >> 2, t4 = lane & 3;
    int qtile = (gridDim.x - 1) - blockIdx.x;           // longest strips first
    int bh = blockIdx.y, b = bh >> 1, h = bh & 1;
    int qb = qtile * 16;
    int nkt = (qtile >> 2) + 1;                         // 64-key tiles needed
    if (tid == 0) *flagp = 0;

    // ---- Phase 1: QK scores into smem ----
    uint32_t a[4];
    #pragma unroll
    for (int i = 0; i < 4; i++) {
        int row = qb + g + (i & 1)*8;
        int k = h*32 + (i >> 1)*16 + t4*4;
        a[i] = *(const uint32_t*)(g_q + (size_t)(b*TSEQ + row)*64 + k);
    }
    for (int nt = w; nt < nkt*8; nt += 8) {
        int n0 = nt*8;
        int c[4] = {0,0,0,0};
        uint32_t bf[2];
        #pragma unroll
        for (int r = 0; r < 2; r++)
            bf[r] = *(const uint32_t*)(g_k + (size_t)(b*TSEQ + n0 + g)*64 + h*32 + r*16 + t4*4);
        mma_s8s8(c, a, bf);
        #pragma unroll
        for (int half = 0; half < 2; half++) {
            int rl = g + half*8;
            int2 v;
            v.x = (int)floorf(__fmul_rn(__fmul_rn(__int2float_rn(c[half*2+0]), 45.0f), 0.00390625f));
            v.y = (int)floorf(__fmul_rn(__fmul_rn(__int2float_rn(c[half*2+1]), 45.0f), 0.00390625f));
            *(int2*)&sc[rl*SC_STR + n0 + t4*2] = v;
        }
    }
    __syncthreads();

    // ---- Phase 2: hw softmax, warp w -> rows w*2, w*2+1 ----
    #pragma unroll
    for (int rr = 0; rr < 2; rr++) {
        int ql = w*2 + rr, q = qb + ql;
        int sreg[32];
        int mymax = -0x7fffffff;
        #pragma unroll
        for (int j = 0; j < 32; j++) {
            int k = j*32 + lane;
            int s = (k <= q) ? sc[ql*SC_STR + k] : -32767;
            sreg[j] = s;
            mymax = max(mymax, s);
        }
        #pragma unroll
        for (int o = 16; o; o >>= 1) mymax = max(mymax, __shfl_xor_sync(0xffffffffu, mymax, o));
        int m = mymax, lsum = 0;
        #pragma unroll
        for (int j = 0; j < 32; j++) {
            int sh = sreg[j] - m;
            int ea;
            if (sh >= -3)       ea = 256 + sh*64;
            else if (sh >= -8)  ea = 64 + (sh + 3)*11;
            else if (sh >= -24) ea = sh + 24;
            else                ea = 0;
            sreg[j] = ea;
            lsum += ea;
        }
        #pragma unroll
        for (int o = 16; o; o >>= 1) lsum += __shfl_xor_sync(0xffffffffu, lsum, o);
        float fs = (float)max(lsum, 1);
        if (m <= -32743 && lane == 0) atomicOr(flagp, 1);   // unreachable in practice; kept for exactness
        #pragma unroll
        for (int j = 0; j < 32; j++) {
            float p = __fmul_rn(__fdiv_rn((float)sreg[j], fs), 255.0f);
            pp[ql*PP_STR + j*32 + lane] = (uint8_t)iclamp((int)rintf(p), 0, 255);
        }
    }
    __syncthreads();

    // ---- Phase 3: PV. warp: nt = w&3 (8 dims), halfw = w>>2 splits key range ----
    int full = *flagp;
    int nks = full ? 32 : nkt*2;                        // 32-key chunks
    int mid = nks >> 1;
    int nt = w & 3, halfw = w >> 2;
    int s0 = halfw ? mid : 0, s1 = halfw ? nks : mid;
    int c[4] = {0,0,0,0};
    for (int ks = s0; ks < s1; ks++) {
        uint32_t aa[4];
        #pragma unroll
        for (int i = 0; i < 4; i++)
            aa[i] = *(const uint32_t*)&pp[(g + (i & 1)*8)*PP_STR + ks*32 + (i >> 1)*16 + t4*4];
        uint32_t bf[2];
        #pragma unroll
        for (int r = 0; r < 2; r++)
            bf[r] = *(const uint32_t*)(g_vt + ((size_t)bh*32 + nt*8 + g)*1024 + ks*32 + r*16 + t4*4);
        mma_u8s8(c, aa, bf);
    }
    if (halfw) {
        #pragma unroll
        for (int i = 0; i < 4; i++) red[(nt*32 + lane)*4 + i] = c[i];
    }
    __syncthreads();
    if (!halfw) {
        #pragma unroll
        for (int idx = 0; idx < 4; idx++) {
            int v = c[idx] + red[(nt*32 + lane)*4 + idx];
            int row = qb + g + (idx >> 1)*8;
            int col = nt*8 + t4*2 + (idx & 1);
            g_a[(size_t)(b*TSEQ + row)*64 + h*32 + col] = (int8_t)(v >> 8);
        }
    }
}

// ============================================================================
// Layer-fused FFN megakernel (unchanged from R6)
// ============================================================================
template<bool LAST>
__global__ void ffn_k(const float* __restrict__ anw, const float* __restrict__ fnw,
                      const float* __restrict__ finw, int l) {
    __shared__ __align__(16) int8_t hs[32][80];
    int tid = threadIdx.x, w = tid >> 5, lane = tid & 31, g = lane >> 2, t4 = lane & 3;
    int mt = w & 1, nh = w >> 1;
    int tbase = blockIdx.x * 32;
    const uint32_t* wl = g_wter + l*WPL;

    {
        uint32_t a[2][4];
        load_a<64>(a, g_a + (size_t)tbase*64, 64, mt, g, t4);
        for (int nt = nh*2; nt < nh*2 + 2; nt++) {
            int n0 = nt*8;
            int c[4] = {0,0,0,0};
            mma_w<64>(c, a, wl + 3072, n0, g, t4);
            #pragma unroll
            for (int idx = 0; idx < 4; idx++) {
                int y = iclamp(c[idx] >> 6, -128, 127);
                int row = tbase + mt*16 + g + (idx >> 1)*8;
                int col = n0 + t4*2 + (idx & 1);
                g_x[row*64 + col] = (int8_t)(g_x[row*64 + col] + y);
            }
        }
    }
    __syncthreads();
    norm32(tbase, fnw + l*64, hs, w, lane);
    __syncthreads();
    {
        uint32_t a[2][4];
        load_a<64>(a, &hs[0][0], 80, mt, g, t4);
        for (int nt = nh*8; nt < nh*8 + 8; nt++) {
            int n0 = nt*8;
            int c[4] = {0,0,0,0};
            mma_w<64>(c, a, wl + 4096, n0, g, t4);
            #pragma unroll
            for (int idx = 0; idx < 4; idx++) {
                int y = iclamp(c[idx] >> 6, -128, 127);
                int row = tbase + mt*16 + g + (idx >> 1)*8;
                int col = n0 + t4*2 + (idx & 1);
                g_u[row*256 + col] = (int8_t)max(y, 0);
            }
        }
    }
    __syncthreads();
    {
        uint32_t a[8][4];
        load_a<256>(a, g_u + (size_t)tbase*256, 256, mt, g, t4);
        for (int nt = nh*2; nt < nh*2 + 2; nt++) {
            int n0 = nt*8;
            int c[4] = {0,0,0,0};
            mma_w<256>(c, a, wl + 8192, n0, g, t4);
            #pragma unroll
            for (int idx = 0; idx < 4; idx++) {
                int y = iclamp(c[idx] >> 6, -128, 127);
                int row = tbase + mt*16 + g + (idx >> 1)*8;
                int col = n0 + t4*2 + (idx & 1);
                g_x[row*64 + col] = (int8_t)(g_x[row*64 + col] + y);
            }
        }
    }
    __syncthreads();
    if (LAST) {
        norm32(tbase, finw, hs, w, lane);
        __syncthreads();
        for (int i = tid; i < 32*16; i += 256) {
            int tl = i >> 4, wd = i & 15;
            ((uint32_t*)(g_h + (size_t)(tbase + tl)*64))[wd] = *(const uint32_t*)&hs[tl][wd*4];
        }
    } else {
        norm32(tbase, anw + (l+1)*64, hs, w, lane);
        __syncthreads();
        qkv_mma(tbase, g_wter + (l+1)*WPL, hs, w, lane);
    }
}

// ============================================================================
// Logits via IMMA (validated bit-exact)
// ============================================================================
__global__ void logits_mma_k(float* __restrict__ out) {
    int w = threadIdx.x >> 5, lane = threadIdx.x & 31;
    int g = lane >> 2, t4 = lane & 3;
    int tb = blockIdx.y * 128 + w * 16;
    int nb = blockIdx.x * 64;

    uint32_t a[2][4];
    const int8_t* xb = g_h + (size_t)tb * 64;
    #pragma unroll
    for (int ks = 0; ks < 2; ks++)
        #pragma unroll
        for (int i = 0; i < 4; i++) {
            int row = g + (i & 1) * 8;
            int k = ks*32 + (i >> 1)*16 + t4*4;
            a[ks][i] = *(const uint32_t*)(xb + row*64 + k);
        }

    #pragma unroll
    for (int nt = 0; nt < 8; nt++) {
        int n0 = nb + nt*8;
        int chi[4] = {0,0,0,0}, clo[4] = {0,0,0,0};
        #pragma unroll
        for (int ks = 0; ks < 2; ks++) {
            uint32_t bh[2], bl[2];
            #pragma unroll
            for (int r = 0; r < 2; r++) {
                int k = ks*32 + r*16 + t4*4;
                bh[r] = *(const uint32_t*)(g_ehi + (size_t)(n0 + g)*64 + k);
                bl[r] = *(const uint32_t*)(g_elo + (size_t)(n0 + g)*64 + k);
            }
            mma_s8s8(chi, a[ks], bh);
            mma_s8u8(clo, a[ks], bl);
        }
        #pragma unroll
        for (int half = 0; half < 2; half++) {
            int row = tb + g + half*8;
            int col = n0 + t4*2;
            float2 val;
            val.x = __fmul_rn(__int2float_rn(chi[half*2+0]*256 + clo[half*2+0]), 1.220703125e-4f);
            val.y = __fmul_rn(__int2float_rn(chi[half*2+1]*256 + clo[half*2+1]), 1.220703125e-4f);
            *(float2*)(out + (size_t)row*VOC + col) = val;
        }
    }
}

// ============================================================================
extern "C" void kernel_launch(void* const* d_in, const int* in_sizes, int n_in,
                              void* d_out, int out_size) {
    const int*   tokens  = (const int*)  d_in[0];
    const float* tok_emb = (const float*)d_in[1];
    const float* pos_emb = (const float*)d_in[2];
    const float* anw     = (const float*)d_in[3];
    const float* qw      = (const float*)d_in[4];
    const float* kw      = (const float*)d_in[5];
    const float* vw      = (const float*)d_in[6];
    const float* ow      = (const float*)d_in[7];
    const float* fnw     = (const float*)d_in[8];
    const float* upw     = (const float*)d_in[9];
    const float* dnw     = (const float*)d_in[10];
    const float* finw    = (const float*)d_in[11];
    float* out = (float*)d_out;

    cudaFuncSetAttribute(attn_fused_k, cudaFuncAttributeMaxDynamicSharedMemorySize, SMEM_ATT);

    prep_w_k<<<24, 256>>>(qw, kw, vw, ow, upw, dnw);
    prep_emb_k<<<(VOC*64)/256, 256>>>(tok_emb);
    emb_qkv0_k<<<128, 256>>>(tokens, tok_emb, pos_emb, anw);

    for (int l = 0; l < 4; l++) {
        attn_fused_k<<<dim3(64, 8), 256, SMEM_ATT>>>();
        if (l < 3) ffn_k<false><<<128, 256>>>(anw, fnw, finw, l);
        else       ffn_k<true ><<<128, 256>>>(anw, fnw, finw, l);
    }
    logits_mma_k<<<dim3(VOC/64, NTOK/128), 256>>>(out);
}

// round 9
// speedup vs baseline: 5.0442x; 1.3087x over previous
#include <cuda_runtime.h>
#include <cstdint>

// ============================================================================
// ZyboGPT hw-accurate quantized transformer forward, bit-exact integer impl.
// B=4 T=1024 D=64 H=2 HD=32 DFF=256 L=4 V=8192
// R8: attention rebuilt — 16 warps/block, warp-per-row causally-bounded
//     vectorized softmax, per-row prob LUT (no per-key fdiv). 12 launches.
// ============================================================================

#define NTOK   4096
#define TSEQ   1024
#define NH     2
#define DFF    256
#define VOC    8192
#define WPL    12288     // u32 words/layer: qkv@0, o@3072, up@4096, down@8192

// attention smem layout (words / bytes)
#define SC_STR 1028                          // score row stride (ints), %32==4
#define PP_STR 1040                          // prob row stride (bytes), /4%32==4
#define LUT_STR 272
#define ATT_SC_B   (16*SC_STR*4)             // 65792
#define ATT_PP_B   (16*PP_STR)               // 16640
#define ATT_LUT_B  (16*LUT_STR)              // 4352
#define ATT_RED_B  (3*4*32*4*4)              // 6144
#define ATT_SMEM   (ATT_SC_B + ATT_PP_B + ATT_LUT_B + ATT_RED_B)

__device__ __align__(16) int8_t  g_x [NTOK*64];
__device__ __align__(16) int8_t  g_q [NTOK*64];
__device__ __align__(16) int8_t  g_k [NTOK*64];
__device__ __align__(16) int8_t  g_v [NTOK*64];
__device__ __align__(16) int8_t  g_vt[8*32*1024];     // [b*H+h][d][t]
__device__ __align__(16) int8_t  g_a [NTOK*64];
__device__ __align__(16) int8_t  g_u [NTOK*DFF];
__device__ __align__(16) int8_t  g_h [NTOK*64];
__device__ __align__(16) uint32_t g_wter[4*WPL];
__device__ __align__(16) int8_t  g_ehi[VOC*64];
__device__ __align__(16) uint8_t g_elo[VOC*64];

__device__ __forceinline__ int iclamp(int v, int lo, int hi) { return min(max(v, lo), hi); }

// ---- IMMA wrappers: m16n8k32, row.col, s32 accum ----
__device__ __forceinline__ void mma_s8s8(int* c, const uint32_t* a, const uint32_t* b) {
    asm volatile("mma.sync.aligned.m16n8k32.row.col.s32.s8.s8.s32 "
        "{%0,%1,%2,%3}, {%4,%5,%6,%7}, {%8,%9}, {%0,%1,%2,%3};"
        : "+r"(c[0]), "+r"(c[1]), "+r"(c[2]), "+r"(c[3])
        : "r"(a[0]), "r"(a[1]), "r"(a[2]), "r"(a[3]), "r"(b[0]), "r"(b[1]));
}
__device__ __forceinline__ void mma_s8u8(int* c, const uint32_t* a, const uint32_t* b) {
    asm volatile("mma.sync.aligned.m16n8k32.row.col.s32.s8.u8.s32 "
        "{%0,%1,%2,%3}, {%4,%5,%6,%7}, {%8,%9}, {%0,%1,%2,%3};"
        : "+r"(c[0]), "+r"(c[1]), "+r"(c[2]), "+r"(c[3])
        : "r"(a[0]), "r"(a[1]), "r"(a[2]), "r"(a[3]), "r"(b[0]), "r"(b[1]));
}
__device__ __forceinline__ void mma_u8s8(int* c, const uint32_t* a, const uint32_t* b) {
    asm volatile("mma.sync.aligned.m16n8k32.row.col.s32.u8.s8.s32 "
        "{%0,%1,%2,%3}, {%4,%5,%6,%7}, {%8,%9}, {%0,%1,%2,%3};"
        : "+r"(c[0]), "+r"(c[1]), "+r"(c[2]), "+r"(c[3])
        : "r"(a[0]), "r"(a[1]), "r"(a[2]), "r"(a[3]), "r"(b[0]), "r"(b[1]));
}

template<int KIN>
__device__ __forceinline__ void load_a(uint32_t a[][4], const int8_t* src, int ldm,
                                       int mt, int g, int t4) {
    #pragma unroll
    for (int ks = 0; ks < KIN/32; ks++)
        #pragma unroll
        for (int i = 0; i < 4; i++) {
            int row = mt*16 + g + (i & 1)*8;
            int k = ks*32 + (i >> 1)*16 + t4*4;
            a[ks][i] = *(const uint32_t*)(src + (size_t)row*ldm + k);
        }
}

template<int KIN>
__device__ __forceinline__ void mma_w(int c[4], const uint32_t a[][4],
                                      const uint32_t* wb, int n0, int g, int t4) {
    #pragma unroll
    for (int ks = 0; ks < KIN/32; ks++) {
        uint32_t bf[2];
        #pragma unroll
        for (int r = 0; r < 2; r++)
            bf[r] = wb[(n0 + g)*(KIN/4) + ks*8 + r*4 + t4];
        mma_s8s8(c, a[ks], bf);
    }
}

// hw PWL exp segment (sh <= 0 always)
__device__ __forceinline__ int pwl_ea(int sh) {
    if (sh >= -3)  return 256 + sh*64;
    if (sh >= -8)  return sh*11 + 97;
    if (sh >= -24) return sh + 24;
    return 0;
}

// ============================================================================
// rmsnorm of 32 tokens into hs[32][80]. 8 warps x 4 tokens.
// ============================================================================
__device__ __forceinline__ void norm32(int tbase, const float* __restrict__ nw,
                                       int8_t hs[32][80], int w, int lane) {
    #pragma unroll
    for (int i = 0; i < 4; i++) {
        int tl = w*4 + i, t = tbase + tl;
        int x0 = g_x[t*64 + lane], x1 = g_x[t*64 + lane + 32];
        int sq = x0*x0 + x1*x1;
        #pragma unroll
        for (int o = 16; o; o >>= 1) sq += __shfl_xor_sync(0xffffffffu, sq, o);
        int lut = min(sq >> 12, 255);
        float bc = (float)(lut*64 + 32);
        int inv = iclamp((int)rintf(__fdiv_rn(16384.0f, __fsqrt_rn(bc))), 0, 16383);
        #pragma unroll
        for (int jj = 0; jj < 2; jj++) {
            int d = lane + jj*32;
            int xi = jj ? x1 : x0;
            int p1 = (xi * inv) >> 8;
            float wc = fminf(fmaxf(nw[d], -2.0f), 2.0f);
            int gq = iclamp((int)rintf(__fmul_rn(wc, 1024.0f)), -32768, 32767);
            float prod = __fmul_rn(__int2float_rn(p1), __int2float_rn(gq));
            int y = (int)floorf(__fmul_rn(prod, 0.0009765625f));
            hs[tl][d] = (int8_t)iclamp(y, -128, 127);
        }
    }
}

__device__ __forceinline__ void qkv_mma(int tbase, const uint32_t* wl,
                                        int8_t hs[32][80], int w, int lane) {
    int g = lane >> 2, t4 = lane & 3, mt = w & 1, nh = w >> 1;
    uint32_t a[2][4];
    load_a<64>(a, &hs[0][0], 80, mt, g, t4);
    for (int nt = nh*6; nt < nh*6 + 6; nt++) {
        int n0 = nt*8;
        int c[4] = {0,0,0,0};
        mma_w<64>(c, a, wl, n0, g, t4);
        #pragma unroll
        for (int idx = 0; idx < 4; idx++) {
            int y = iclamp(c[idx] >> 6, -128, 127);
            int row = tbase + mt*16 + g + (idx >> 1)*8;
            int col = n0 + t4*2 + (idx & 1);
            if (col < 64)       g_q[row*64 + col] = (int8_t)y;
            else if (col < 128) g_k[row*64 + col - 64] = (int8_t)y;
            else {
                int oo = col - 128;
                g_v[row*64 + oo] = (int8_t)y;
                g_vt[((row >> 10)*2 + (oo >> 5))*32768 + (oo & 31)*1024 + (row & 1023)] = (int8_t)y;
            }
        }
    }
}

// ============================================================================
// Prep kernels (unchanged numerics)
// ============================================================================
__global__ void prep_w_k(const float* __restrict__ qw, const float* __restrict__ kw,
                         const float* __restrict__ vw, const float* __restrict__ ow,
                         const float* __restrict__ upw, const float* __restrict__ dnw) {
    int id = blockIdx.x, l = id / 6, mt = id % 6, tid = threadIdx.x;
    const float* w; int N; uint32_t* dst;
    switch (mt) {
        case 0: w = qw  + l*4096;  N = 4096;  dst = g_wter + l*WPL + 0;    break;
        case 1: w = kw  + l*4096;  N = 4096;  dst = g_wter + l*WPL + 1024; break;
        case 2: w = vw  + l*4096;  N = 4096;  dst = g_wter + l*WPL + 2048; break;
        case 3: w = ow  + l*4096;  N = 4096;  dst = g_wter + l*WPL + 3072; break;
        case 4: w = upw + l*16384; N = 16384; dst = g_wter + l*WPL + 4096; break;
        default:w = dnw + l*16384; N = 16384; dst = g_wter + l*WPL + 8192; break;
    }
    __shared__ float rs[256];
    float s = 0.0f;
    for (int i = tid; i < N; i += 256) s += fabsf(w[i]);
    rs[tid] = s; __syncthreads();
    for (int st = 128; st > 0; st >>= 1) {
        if (tid < st) rs[tid] += rs[tid + st];
        __syncthreads();
    }
    float scale = fmaxf(__fdiv_rn(rs[0], (float)N), 1e-5f);
    for (int wi = tid; wi < N / 4; wi += 256) {
        uint32_t pk = 0;
        #pragma unroll
        for (int j = 0; j < 4; j++) {
            int tv = iclamp((int)rintf(__fdiv_rn(w[wi*4 + j], scale)), -1, 1);
            pk |= ((uint32_t)(tv & 255)) << (8 * j);
        }
        dst[wi] = pk;
    }
}

__global__ void prep_emb_k(const float* __restrict__ temb) {
    int i = blockIdx.x * blockDim.x + threadIdx.x;
    if (i >= VOC * 64) return;
    int q = iclamp((int)rintf(__fmul_rn(temb[i], 1024.0f)), -32768, 32767);
    g_ehi[i] = (int8_t)(q >> 8);
    g_elo[i] = (uint8_t)(q & 255);
}

__global__ void emb_qkv0_k(const int* __restrict__ tokens, const float* __restrict__ temb,
                           const float* __restrict__ pemb, const float* __restrict__ anw) {
    __shared__ __align__(16) int8_t hs[32][80];
    int tid = threadIdx.x, w = tid >> 5, lane = tid & 31;
    int tbase = blockIdx.x * 32;
    for (int i = tid; i < 32*64; i += 256) {
        int tl = i >> 6, d = i & 63, t = tbase + tl;
        int tok = tokens[t];
        int tq = iclamp((int)rintf(__fmul_rn(temb[tok*64 + d], 1024.0f)), -32768, 32767);
        int pq = iclamp((int)rintf(__fmul_rn(pemb[(t & 1023)*64 + d], 1024.0f)), -32768, 32767);
        g_x[t*64 + d] = (int8_t)((tq + pq) >> 3);
    }
    __syncthreads();
    norm32(tbase, anw, hs, w, lane);
    __syncthreads();
    qkv_mma(tbase, g_wter, hs, w, lane);
}

// ============================================================================
// Fused attention R8. Block = 512 thr (16 warps), one (bh, 16-row) strip.
// grid (64 reversed, 8). Phase1 QK->smem; Phase2 warp-per-row bounded softmax
// with prob LUT; Phase3 PV with 4-way key split.
// Note: max over a row >= diag score >= 0 > -32743, so the all-masked softmax
// regime is unreachable; masked keys have ea=0 -> prob=0 exactly.
// ============================================================================
__global__ __launch_bounds__(512, 2) void attn_fused_k() {
    extern __shared__ int sm[];
    int*      sc  = sm;                                   // [16][SC_STR]
    uint8_t*  pp  = (uint8_t*)(sc + 16*SC_STR);           // [16][PP_STR]
    uint8_t*  lut = pp + 16*PP_STR;                       // [16][LUT_STR]
    int*      red = (int*)(lut + 16*LUT_STR);             // [3][4][32][4]

    int tid = threadIdx.x, w = tid >> 5, lane = tid & 31, g = lane >> 2, t4 = lane & 3;
    int qtile = 63 - blockIdx.x;                          // longest strips first
    int bh = blockIdx.y, b = bh >> 1, h = bh & 1;
    int qb = qtile * 16;
    int ntiles = 2*qtile + 2;                             // 8-key n-tiles (= qb+16 keys)
    int nks32 = (qb + 16 + 31) >> 5;                      // 32-key chunks for PV

    // ---- Phase 1: QK scores into smem ----
    {
        uint32_t a[4];
        #pragma unroll
        for (int i = 0; i < 4; i++) {
            int row = qb + g + (i & 1)*8;
            int k = h*32 + (i >> 1)*16 + t4*4;
            a[i] = *(const uint32_t*)(g_q + (size_t)(b*TSEQ + row)*64 + k);
        }
        for (int nt = w; nt < ntiles; nt += 16) {
            int n0 = nt*8;
            int c[4] = {0,0,0,0};
            uint32_t bf[2];
            #pragma unroll
            for (int r = 0; r < 2; r++)
                bf[r] = *(const uint32_t*)(g_k + (size_t)(b*TSEQ + n0 + g)*64 + h*32 + r*16 + t4*4);
            mma_s8s8(c, a, bf);
            #pragma unroll
            for (int half = 0; half < 2; half++) {
                int rl = g + half*8;
                int2 v;
                v.x = (int)floorf(__fmul_rn(__fmul_rn(__int2float_rn(c[half*2+0]), 45.0f), 0.00390625f));
                v.y = (int)floorf(__fmul_rn(__fmul_rn(__int2float_rn(c[half*2+1]), 45.0f), 0.00390625f));
                *(int2*)&sc[rl*SC_STR + n0 + t4*2] = v;
            }
        }
    }
    __syncthreads();

    // ---- Phase 2: softmax, one warp per row ----
    {
        int ql = w, q = qb + ql;
        int* srow = sc + ql*SC_STR;
        int nsc = (q >> 7) + 1;                           // 128-key superchunks
        int kbase = lane*4;

        // pass 1: row max (masked keys = -32767, never the max since diag >= 0)
        int m = -32767;
        for (int sb = 0; sb < nsc; sb++) {
            int4 s4 = *(const int4*)&srow[sb*128 + kbase];
            int k0 = sb*128 + kbase;
            if (k0 + 0 > q) s4.x = -32767;
            if (k0 + 1 > q) s4.y = -32767;
            if (k0 + 2 > q) s4.z = -32767;
            if (k0 + 3 > q) s4.w = -32767;
            m = max(m, max(max(s4.x, s4.y), max(s4.z, s4.w)));
        }
        #pragma unroll
        for (int o = 16; o; o >>= 1) m = max(m, __shfl_xor_sync(0xffffffffu, m, o));

        // pass 2: sum of PWL ea
        int lsum = 0;
        for (int sb = 0; sb < nsc; sb++) {
            int4 s4 = *(const int4*)&srow[sb*128 + kbase];
            int k0 = sb*128 + kbase;
            if (k0 + 0 > q) s4.x = -32767;
            if (k0 + 1 > q) s4.y = -32767;
            if (k0 + 2 > q) s4.z = -32767;
            if (k0 + 3 > q) s4.w = -32767;
            lsum += pwl_ea(s4.x - m) + pwl_ea(s4.y - m) + pwl_ea(s4.z - m) + pwl_ea(s4.w - m);
        }
        #pragma unroll
        for (int o = 16; o; o >>= 1) lsum += __shfl_xor_sync(0xffffffffu, lsum, o);
        float fs = (float)max(lsum, 1);

        // per-row prob LUT over ea in [0,256]
        uint8_t* lrow = lut + ql*LUT_STR;
        #pragma unroll
        for (int r = 0; r < 9; r++) {
            int idx = r*32 + lane;
            if (idx <= 256) {
                float p = __fmul_rn(__fdiv_rn((float)idx, fs), 255.0f);
                lrow[idx] = (uint8_t)iclamp((int)rintf(p), 0, 255);
            }
        }
        __syncwarp();

        // pass 3: probs -> pp (packed u32, 4 keys/lane)
        uint8_t* prow = pp + ql*PP_STR;
        for (int sb = 0; sb < nsc; sb++) {
            int4 s4 = *(const int4*)&srow[sb*128 + kbase];
            int k0 = sb*128 + kbase;
            if (k0 + 0 > q) s4.x = -32767;
            if (k0 + 1 > q) s4.y = -32767;
            if (k0 + 2 > q) s4.z = -32767;
            if (k0 + 3 > q) s4.w = -32767;
            uint32_t pk = (uint32_t)lrow[pwl_ea(s4.x - m)]
                        | ((uint32_t)lrow[pwl_ea(s4.y - m)] << 8)
                        | ((uint32_t)lrow[pwl_ea(s4.z - m)] << 16)
                        | ((uint32_t)lrow[pwl_ea(s4.w - m)] << 24);
            *(uint32_t*)&prow[k0] = pk;
        }
    }
    __syncthreads();

    // ---- Phase 3: PV, warp = (nt dims, kq key-quarter) ----
    {
        int nt = w & 3, kq = w >> 2;
        int c0 = (kq * nks32) >> 2, c1 = ((kq + 1) * nks32) >> 2;
        int c[4] = {0,0,0,0};
        for (int ks = c0; ks < c1; ks++) {
            uint32_t aa[4];
            #pragma unroll
            for (int i = 0; i < 4; i++)
                aa[i] = *(const uint32_t*)&pp[(g + (i & 1)*8)*PP_STR + ks*32 + (i >> 1)*16 + t4*4];
            uint32_t bf[2];
            #pragma unroll
            for (int r = 0; r < 2; r++)
                bf[r] = *(const uint32_t*)(g_vt + ((size_t)bh*32 + nt*8 + g)*1024 + ks*32 + r*16 + t4*4);
            mma_u8s8(c, aa, bf);
        }
        if (kq > 0) {
            #pragma unroll
            for (int i = 0; i < 4; i++)
                red[((kq - 1)*4 + nt)*128 + lane*4 + i] = c[i];
        }
        __syncthreads();
        if (kq == 0) {
            #pragma unroll
            for (int idx = 0; idx < 4; idx++) {
                int v = c[idx];
                #pragma unroll
                for (int r = 0; r < 3; r++)
                    v += red[(r*4 + nt)*128 + lane*4 + idx];
                int row = qb + g + (idx >> 1)*8;
                int col = nt*8 + t4*2 + (idx & 1);
                g_a[(size_t)(b*TSEQ + row)*64 + h*32 + col] = (int8_t)(v >> 8);
            }
        }
    }
}

// ============================================================================
// Layer-fused FFN megakernel (unchanged)
// ============================================================================
template<bool LAST>
__global__ void ffn_k(const float* __restrict__ anw, const float* __restrict__ fnw,
                      const float* __restrict__ finw, int l) {
    __shared__ __align__(16) int8_t hs[32][80];
    int tid = threadIdx.x, w = tid >> 5, lane = tid & 31, g = lane >> 2, t4 = lane & 3;
    int mt = w & 1, nh = w >> 1;
    int tbase = blockIdx.x * 32;
    const uint32_t* wl = g_wter + l*WPL;

    {
        uint32_t a[2][4];
        load_a<64>(a, g_a + (size_t)tbase*64, 64, mt, g, t4);
        for (int nt = nh*2; nt < nh*2 + 2; nt++) {
            int n0 = nt*8;
            int c[4] = {0,0,0,0};
            mma_w<64>(c, a, wl + 3072, n0, g, t4);
            #pragma unroll
            for (int idx = 0; idx < 4; idx++) {
                int y = iclamp(c[idx] >> 6, -128, 127);
                int row = tbase + mt*16 + g + (idx >> 1)*8;
                int col = n0 + t4*2 + (idx & 1);
                g_x[row*64 + col] = (int8_t)(g_x[row*64 + col] + y);
            }
        }
    }
    __syncthreads();
    norm32(tbase, fnw + l*64, hs, w, lane);
    __syncthreads();
    {
        uint32_t a[2][4];
        load_a<64>(a, &hs[0][0], 80, mt, g, t4);
        for (int nt = nh*8; nt < nh*8 + 8; nt++) {
            int n0 = nt*8;
            int c[4] = {0,0,0,0};
            mma_w<64>(c, a, wl + 4096, n0, g, t4);
            #pragma unroll
            for (int idx = 0; idx < 4; idx++) {
                int y = iclamp(c[idx] >> 6, -128, 127);
                int row = tbase + mt*16 + g + (idx >> 1)*8;
                int col = n0 + t4*2 + (idx & 1);
                g_u[row*256 + col] = (int8_t)max(y, 0);
            }
        }
    }
    __syncthreads();
    {
        uint32_t a[8][4];
        load_a<256>(a, g_u + (size_t)tbase*256, 256, mt, g, t4);
        for (int nt = nh*2; nt < nh*2 + 2; nt++) {
            int n0 = nt*8;
            int c[4] = {0,0,0,0};
            mma_w<256>(c, a, wl + 8192, n0, g, t4);
            #pragma unroll
            for (int idx = 0; idx < 4; idx++) {
                int y = iclamp(c[idx] >> 6, -128, 127);
                int row = tbase + mt*16 + g + (idx >> 1)*8;
                int col = n0 + t4*2 + (idx & 1);
                g_x[row*64 + col] = (int8_t)(g_x[row*64 + col] + y);
            }
        }
    }
    __syncthreads();
    if (LAST) {
        norm32(tbase, finw, hs, w, lane);
        __syncthreads();
        for (int i = tid; i < 32*16; i += 256) {
            int tl = i >> 4, wd = i & 15;
            ((uint32_t*)(g_h + (size_t)(tbase + tl)*64))[wd] = *(const uint32_t*)&hs[tl][wd*4];
        }
    } else {
        norm32(tbase, anw + (l+1)*64, hs, w, lane);
        __syncthreads();
        qkv_mma(tbase, g_wter + (l+1)*WPL, hs, w, lane);
    }
}

// ============================================================================
// Logits via IMMA (validated bit-exact)
// ============================================================================
__global__ void logits_mma_k(float* __restrict__ out) {
    int w = threadIdx.x >> 5, lane = threadIdx.x & 31;
    int g = lane >> 2, t4 = lane & 3;
    int tb = blockIdx.y * 128 + w * 16;
    int nb = blockIdx.x * 64;

    uint32_t a[2][4];
    const int8_t* xb = g_h + (size_t)tb * 64;
    #pragma unroll
    for (int ks = 0; ks < 2; ks++)
        #pragma unroll
        for (int i = 0; i < 4; i++) {
            int row = g + (i & 1) * 8;
            int k = ks*32 + (i >> 1)*16 + t4*4;
            a[ks][i] = *(const uint32_t*)(xb + row*64 + k);
        }

    #pragma unroll
    for (int nt = 0; nt < 8; nt++) {
        int n0 = nb + nt*8;
        int chi[4] = {0,0,0,0}, clo[4] = {0,0,0,0};
        #pragma unroll
        for (int ks = 0; ks < 2; ks++) {
            uint32_t bh[2], bl[2];
            #pragma unroll
            for (int r = 0; r < 2; r++) {
                int k = ks*32 + r*16 + t4*4;
                bh[r] = *(const uint32_t*)(g_ehi + (size_t)(n0 + g)*64 + k);
                bl[r] = *(const uint32_t*)(g_elo + (size_t)(n0 + g)*64 + k);
            }
            mma_s8s8(chi, a[ks], bh);
            mma_s8u8(clo, a[ks], bl);
        }
        #pragma unroll
        for (int half = 0; half < 2; half++) {
            int row = tb + g + half*8;
            int col = n0 + t4*2;
            float2 val;
            val.x = __fmul_rn(__int2float_rn(chi[half*2+0]*256 + clo[half*2+0]), 1.220703125e-4f);
            val.y = __fmul_rn(__int2float_rn(chi[half*2+1]*256 + clo[half*2+1]), 1.220703125e-4f);
            *(float2*)(out + (size_t)row*VOC + col) = val;
        }
    }
}

// ============================================================================
extern "C" void kernel_launch(void* const* d_in, const int* in_sizes, int n_in,
                              void* d_out, int out_size) {
    const int*   tokens  = (const int*)  d_in[0];
    const float* tok_emb = (const float*)d_in[1];
    const float* pos_emb = (const float*)d_in[2];
    const float* anw     = (const float*)d_in[3];
    const float* qw      = (const float*)d_in[4];
    const float* kw      = (const float*)d_in[5];
    const float* vw      = (const float*)d_in[6];
    const float* ow      = (const float*)d_in[7];
    const float* fnw     = (const float*)d_in[8];
    const float* upw     = (const float*)d_in[9];
    const float* dnw     = (const float*)d_in[10];
    const float* finw    = (const float*)d_in[11];
    float* out = (float*)d_out;

    cudaFuncSetAttribute(attn_fused_k, cudaFuncAttributeMaxDynamicSharedMemorySize, ATT_SMEM);

    prep_w_k<<<24, 256>>>(qw, kw, vw, ow, upw, dnw);
    prep_emb_k<<<(VOC*64)/256, 256>>>(tok_emb);
    emb_qkv0_k<<<128, 256>>>(tokens, tok_emb, pos_emb, anw);

    for (int l = 0; l < 4; l++) {
        attn_fused_k<<<dim3(64, 8), 512, ATT_SMEM>>>();
        if (l < 3) ffn_k<false><<<128, 256>>>(anw, fnw, finw, l);
        else       ffn_k<true ><<<128, 256>>>(anw, fnw, finw, l);
    }
    logits_mma_k<<<dim3(VOC/64, NTOK/128), 256>>>(out);
}

// round 10
// speedup vs baseline: 5.5771x; 1.1057x over previous
#include <cuda_runtime.h>
#include <cstdint>

// ============================================================================
// ZyboGPT hw-accurate quantized transformer forward, bit-exact integer impl.
// B=4 T=1024 D=64 H=2 HD=32 DFF=256 L=4 V=8192
// R9: softmax full/partial chunk split (masks only in partial chunk),
//     ea cached in smem between passes, 16-token blocks for token-local kernels.
// ============================================================================

#define NTOK   4096
#define TSEQ   1024
#define NH     2
#define DFF    256
#define VOC    8192
#define WPL    12288     // u32 words/layer: qkv@0, o@3072, up@4096, down@8192

// attention smem layout
#define SC_STR 1028                          // score/ea row stride (ints)
#define PP_STR 1040                          // prob row stride (bytes)
#define LUT_STR 272
#define ATT_SC_B   (16*SC_STR*4)
#define ATT_PP_B   (16*PP_STR)
#define ATT_LUT_B  (16*LUT_STR)
#define ATT_RED_B  (3*4*32*4*4)
#define ATT_SMEM   (ATT_SC_B + ATT_PP_B + ATT_LUT_B + ATT_RED_B)

__device__ __align__(16) int8_t  g_x [NTOK*64];
__device__ __align__(16) int8_t  g_q [NTOK*64];
__device__ __align__(16) int8_t  g_k [NTOK*64];
__device__ __align__(16) int8_t  g_v [NTOK*64];
__device__ __align__(16) int8_t  g_vt[8*32*1024];     // [b*H+h][d][t]
__device__ __align__(16) int8_t  g_a [NTOK*64];
__device__ __align__(16) int8_t  g_u [NTOK*DFF];
__device__ __align__(16) int8_t  g_h [NTOK*64];
__device__ __align__(16) uint32_t g_wter[4*WPL];
__device__ __align__(16) int8_t  g_ehi[VOC*64];
__device__ __align__(16) uint8_t g_elo[VOC*64];

__device__ __forceinline__ int iclamp(int v, int lo, int hi) { return min(max(v, lo), hi); }

// ---- IMMA wrappers: m16n8k32, row.col, s32 accum ----
__device__ __forceinline__ void mma_s8s8(int* c, const uint32_t* a, const uint32_t* b) {
    asm volatile("mma.sync.aligned.m16n8k32.row.col.s32.s8.s8.s32 "
        "{%0,%1,%2,%3}, {%4,%5,%6,%7}, {%8,%9}, {%0,%1,%2,%3};"
        : "+r"(c[0]), "+r"(c[1]), "+r"(c[2]), "+r"(c[3])
        : "r"(a[0]), "r"(a[1]), "r"(a[2]), "r"(a[3]), "r"(b[0]), "r"(b[1]));
}
__device__ __forceinline__ void mma_s8u8(int* c, const uint32_t* a, const uint32_t* b) {
    asm volatile("mma.sync.aligned.m16n8k32.row.col.s32.s8.u8.s32 "
        "{%0,%1,%2,%3}, {%4,%5,%6,%7}, {%8,%9}, {%0,%1,%2,%3};"
        : "+r"(c[0]), "+r"(c[1]), "+r"(c[2]), "+r"(c[3])
        : "r"(a[0]), "r"(a[1]), "r"(a[2]), "r"(a[3]), "r"(b[0]), "r"(b[1]));
}
__device__ __forceinline__ void mma_u8s8(int* c, const uint32_t* a, const uint32_t* b) {
    asm volatile("mma.sync.aligned.m16n8k32.row.col.s32.u8.s8.s32 "
        "{%0,%1,%2,%3}, {%4,%5,%6,%7}, {%8,%9}, {%0,%1,%2,%3};"
        : "+r"(c[0]), "+r"(c[1]), "+r"(c[2]), "+r"(c[3])
        : "r"(a[0]), "r"(a[1]), "r"(a[2]), "r"(a[3]), "r"(b[0]), "r"(b[1]));
}

template<int KIN>
__device__ __forceinline__ void load_a(uint32_t a[][4], const int8_t* src, int ldm,
                                       int mt, int g, int t4) {
    #pragma unroll
    for (int ks = 0; ks < KIN/32; ks++)
        #pragma unroll
        for (int i = 0; i < 4; i++) {
            int row = mt*16 + g + (i & 1)*8;
            int k = ks*32 + (i >> 1)*16 + t4*4;
            a[ks][i] = *(const uint32_t*)(src + (size_t)row*ldm + k);
        }
}

template<int KIN>
__device__ __forceinline__ void mma_w(int c[4], const uint32_t a[][4],
                                      const uint32_t* wb, int n0, int g, int t4) {
    #pragma unroll
    for (int ks = 0; ks < KIN/32; ks++) {
        uint32_t bf[2];
        #pragma unroll
        for (int r = 0; r < 2; r++)
            bf[r] = wb[(n0 + g)*(KIN/4) + ks*8 + r*4 + t4];
        mma_s8s8(c, a[ks], bf);
    }
}

// hw PWL exp segment (sh <= 0 always)
__device__ __forceinline__ int pwl_ea(int sh) {
    if (sh >= -3)  return 256 + sh*64;
    if (sh >= -8)  return sh*11 + 97;
    if (sh >= -24) return sh + 24;
    return 0;
}

// ============================================================================
// rmsnorm of 16 tokens into hs[16][80]. 8 warps x 2 tokens.
// ============================================================================
__device__ __forceinline__ void norm16(int tbase, const float* __restrict__ nw,
                                       int8_t hs[16][80], int w, int lane) {
    #pragma unroll
    for (int i = 0; i < 2; i++) {
        int tl = w*2 + i, t = tbase + tl;
        int x0 = g_x[t*64 + lane], x1 = g_x[t*64 + lane + 32];
        int sq = x0*x0 + x1*x1;
        #pragma unroll
        for (int o = 16; o; o >>= 1) sq += __shfl_xor_sync(0xffffffffu, sq, o);
        int lut = min(sq >> 12, 255);
        float bc = (float)(lut*64 + 32);
        int inv = iclamp((int)rintf(__fdiv_rn(16384.0f, __fsqrt_rn(bc))), 0, 16383);
        #pragma unroll
        for (int jj = 0; jj < 2; jj++) {
            int d = lane + jj*32;
            int xi = jj ? x1 : x0;
            int p1 = (xi * inv) >> 8;
            float wc = fminf(fmaxf(nw[d], -2.0f), 2.0f);
            int gq = iclamp((int)rintf(__fmul_rn(wc, 1024.0f)), -32768, 32767);
            float prod = __fmul_rn(__int2float_rn(p1), __int2float_rn(gq));
            int y = (int)floorf(__fmul_rn(prod, 0.0009765625f));
            hs[tl][d] = (int8_t)iclamp(y, -128, 127);
        }
    }
}

// QKV projection for 16 tokens. 8 warps x 3 n-tiles.
__device__ __forceinline__ void qkv_mma16(int tbase, const uint32_t* wl,
                                          int8_t hs[16][80], int w, int lane) {
    int g = lane >> 2, t4 = lane & 3;
    uint32_t a[2][4];
    load_a<64>(a, &hs[0][0], 80, 0, g, t4);
    for (int nt = w*3; nt < w*3 + 3; nt++) {
        int n0 = nt*8;
        int c[4] = {0,0,0,0};
        mma_w<64>(c, a, wl, n0, g, t4);
        #pragma unroll
        for (int idx = 0; idx < 4; idx++) {
            int y = iclamp(c[idx] >> 6, -128, 127);
            int row = tbase + g + (idx >> 1)*8;
            int col = n0 + t4*2 + (idx & 1);
            if (col < 64)       g_q[row*64 + col] = (int8_t)y;
            else if (col < 128) g_k[row*64 + col - 64] = (int8_t)y;
            else {
                int oo = col - 128;
                g_v[row*64 + oo] = (int8_t)y;
                g_vt[((row >> 10)*2 + (oo >> 5))*32768 + (oo & 31)*1024 + (row & 1023)] = (int8_t)y;
            }
        }
    }
}

// ============================================================================
// Prep kernels (unchanged numerics)
// ============================================================================
__global__ void prep_w_k(const float* __restrict__ qw, const float* __restrict__ kw,
                         const float* __restrict__ vw, const float* __restrict__ ow,
                         const float* __restrict__ upw, const float* __restrict__ dnw) {
    int id = blockIdx.x, l = id / 6, mt = id % 6, tid = threadIdx.x;
    const float* w; int N; uint32_t* dst;
    switch (mt) {
        case 0: w = qw  + l*4096;  N = 4096;  dst = g_wter + l*WPL + 0;    break;
        case 1: w = kw  + l*4096;  N = 4096;  dst = g_wter + l*WPL + 1024; break;
        case 2: w = vw  + l*4096;  N = 4096;  dst = g_wter + l*WPL + 2048; break;
        case 3: w = ow  + l*4096;  N = 4096;  dst = g_wter + l*WPL + 3072; break;
        case 4: w = upw + l*16384; N = 16384; dst = g_wter + l*WPL + 4096; break;
        default:w = dnw + l*16384; N = 16384; dst = g_wter + l*WPL + 8192; break;
    }
    __shared__ float rs[256];
    float s = 0.0f;
    for (int i = tid; i < N; i += 256) s += fabsf(w[i]);
    rs[tid] = s; __syncthreads();
    for (int st = 128; st > 0; st >>= 1) {
        if (tid < st) rs[tid] += rs[tid + st];
        __syncthreads();
    }
    float scale = fmaxf(__fdiv_rn(rs[0], (float)N), 1e-5f);
    for (int wi = tid; wi < N / 4; wi += 256) {
        uint32_t pk = 0;
        #pragma unroll
        for (int j = 0; j < 4; j++) {
            int tv = iclamp((int)rintf(__fdiv_rn(w[wi*4 + j], scale)), -1, 1);
            pk |= ((uint32_t)(tv & 255)) << (8 * j);
        }
        dst[wi] = pk;
    }
}

__global__ void prep_emb_k(const float* __restrict__ temb) {
    int i = blockIdx.x * blockDim.x + threadIdx.x;
    if (i >= VOC * 64) return;
    int q = iclamp((int)rintf(__fmul_rn(temb[i], 1024.0f)), -32768, 32767);
    g_ehi[i] = (int8_t)(q >> 8);
    g_elo[i] = (uint8_t)(q & 255);
}

__global__ void emb_qkv0_k(const int* __restrict__ tokens, const float* __restrict__ temb,
                           const float* __restrict__ pemb, const float* __restrict__ anw) {
    __shared__ __align__(16) int8_t hs[16][80];
    int tid = threadIdx.x, w = tid >> 5, lane = tid & 31;
    int tbase = blockIdx.x * 16;
    for (int i = tid; i < 16*64; i += 256) {
        int tl = i >> 6, d = i & 63, t = tbase + tl;
        int tok = tokens[t];
        int tq = iclamp((int)rintf(__fmul_rn(temb[tok*64 + d], 1024.0f)), -32768, 32767);
        int pq = iclamp((int)rintf(__fmul_rn(pemb[(t & 1023)*64 + d], 1024.0f)), -32768, 32767);
        g_x[t*64 + d] = (int8_t)((tq + pq) >> 3);
    }
    __syncthreads();
    norm16(tbase, anw, hs, w, lane);
    __syncthreads();
    qkv_mma16(tbase, g_wter, hs, w, lane);
}

// ============================================================================
// Fused attention R9. Block = 512 thr, one (bh, 16-row) strip, grid (64 rev, 8).
// Softmax: full superchunks need NO causal masking (row max >= diag >= 0, all
// in-strip masked keys and any unwritten smem lie in the single partial chunk).
// Pass2 caches ea back into sc; pass3 is a pure LUT gather.
// ============================================================================
__global__ __launch_bounds__(512, 2) void attn_fused_k() {
    extern __shared__ int sm[];
    int*      sc  = sm;                                   // [16][SC_STR] scores->ea
    uint8_t*  pp  = (uint8_t*)(sc + 16*SC_STR);           // [16][PP_STR]
    uint8_t*  lut = pp + 16*PP_STR;                       // [16][LUT_STR]
    int*      red = (int*)(lut + 16*LUT_STR);             // [3][4][32][4]

    int tid = threadIdx.x, w = tid >> 5, lane = tid & 31, g = lane >> 2, t4 = lane & 3;
    int qtile = 63 - blockIdx.x;                          // longest strips first
    int bh = blockIdx.y, b = bh >> 1, h = bh & 1;
    int qb = qtile * 16;
    int ntiles = 2*qtile + 2;                             // 8-key n-tiles (= qb+16 keys)
    int nks32 = (qb + 16 + 31) >> 5;                      // 32-key chunks for PV

    // ---- Phase 1: QK scores into smem ----
    {
        uint32_t a[4];
        #pragma unroll
        for (int i = 0; i < 4; i++) {
            int row = qb + g + (i & 1)*8;
            int k = h*32 + (i >> 1)*16 + t4*4;
            a[i] = *(const uint32_t*)(g_q + (size_t)(b*TSEQ + row)*64 + k);
        }
        for (int nt = w; nt < ntiles; nt += 16) {
            int n0 = nt*8;
            int c[4] = {0,0,0,0};
            uint32_t bf[2];
            #pragma unroll
            for (int r = 0; r < 2; r++)
                bf[r] = *(const uint32_t*)(g_k + (size_t)(b*TSEQ + n0 + g)*64 + h*32 + r*16 + t4*4);
            mma_s8s8(c, a, bf);
            #pragma unroll
            for (int half = 0; half < 2; half++) {
                int rl = g + half*8;
                int2 v;
                v.x = __float2int_rd(__fmul_rn(__fmul_rn(__int2float_rn(c[half*2+0]), 45.0f), 0.00390625f));
                v.y = __float2int_rd(__fmul_rn(__fmul_rn(__int2float_rn(c[half*2+1]), 45.0f), 0.00390625f));
                *(int2*)&sc[rl*SC_STR + n0 + t4*2] = v;
            }
        }
    }
    __syncthreads();

    // ---- Phase 2: softmax, one warp per row ----
    {
        int ql = w, q = qb + ql;
        int* srow = sc + ql*SC_STR;
        int kbase = lane*4;
        int nfull = (q + 1) >> 7;                         // fully-valid superchunks
        int haspart = ((q + 1) & 127) != 0;

        // pass 1: row max (no masks in full chunks)
        int m = -32767;
        for (int sb = 0; sb < nfull; sb++) {
            int4 s4 = *(const int4*)&srow[sb*128 + kbase];
            m = max(m, max(max(s4.x, s4.y), max(s4.z, s4.w)));
        }
        if (haspart) {
            int k0 = nfull*128 + kbase;
            int4 s4 = *(const int4*)&srow[k0];
            if (k0 + 0 > q) s4.x = -32767;
            if (k0 + 1 > q) s4.y = -32767;
            if (k0 + 2 > q) s4.z = -32767;
            if (k0 + 3 > q) s4.w = -32767;
            m = max(m, max(max(s4.x, s4.y), max(s4.z, s4.w)));
        }
        #pragma unroll
        for (int o = 16; o; o >>= 1) m = max(m, __shfl_xor_sync(0xffffffffu, m, o));

        // pass 2: ea, cached back into sc, and sum
        int lsum = 0;
        for (int sb = 0; sb < nfull; sb++) {
            int4 s4 = *(const int4*)&srow[sb*128 + kbase];
            s4.x = pwl_ea(s4.x - m); s4.y = pwl_ea(s4.y - m);
            s4.z = pwl_ea(s4.z - m); s4.w = pwl_ea(s4.w - m);
            lsum += s4.x + s4.y + s4.z + s4.w;
            *(int4*)&srow[sb*128 + kbase] = s4;
        }
        if (haspart) {
            int k0 = nfull*128 + kbase;
            int4 s4 = *(const int4*)&srow[k0];
            s4.x = (k0 + 0 > q) ? 0 : pwl_ea(s4.x - m);
            s4.y = (k0 + 1 > q) ? 0 : pwl_ea(s4.y - m);
            s4.z = (k0 + 2 > q) ? 0 : pwl_ea(s4.z - m);
            s4.w = (k0 + 3 > q) ? 0 : pwl_ea(s4.w - m);
            lsum += s4.x + s4.y + s4.z + s4.w;
            *(int4*)&srow[k0] = s4;
        }
        #pragma unroll
        for (int o = 16; o; o >>= 1) lsum += __shfl_xor_sync(0xffffffffu, lsum, o);
        float fs = (float)max(lsum, 1);

        // per-row prob LUT over ea in [0,256]  (lut[0] = 0 exactly)
        uint8_t* lrow = lut + ql*LUT_STR;
        #pragma unroll
        for (int r = 0; r < 9; r++) {
            int idx = r*32 + lane;
            if (idx <= 256) {
                float p = __fmul_rn(__fdiv_rn((float)idx, fs), 255.0f);
                lrow[idx] = (uint8_t)iclamp((int)rintf(p), 0, 255);
            }
        }
        __syncwarp();

        // pass 3: LUT gather, pack 4 probs per u32
        uint8_t* prow = pp + ql*PP_STR;
        int nsc = nfull + haspart;
        for (int sb = 0; sb < nsc; sb++) {
            int k0 = sb*128 + kbase;
            int4 e4 = *(const int4*)&srow[k0];
            uint32_t pk = (uint32_t)lrow[e4.x]
                        | ((uint32_t)lrow[e4.y] << 8)
                        | ((uint32_t)lrow[e4.z] << 16)
                        | ((uint32_t)lrow[e4.w] << 24);
            *(uint32_t*)&prow[k0] = pk;
        }
    }
    __syncthreads();

    // ---- Phase 3: PV, warp = (nt dims, kq key-quarter) ----
    {
        int nt = w & 3, kq = w >> 2;
        int c0 = (kq * nks32) >> 2, c1 = ((kq + 1) * nks32) >> 2;
        int c[4] = {0,0,0,0};
        for (int ks = c0; ks < c1; ks++) {
            uint32_t aa[4];
            #pragma unroll
            for (int i = 0; i < 4; i++)
                aa[i] = *(const uint32_t*)&pp[(g + (i & 1)*8)*PP_STR + ks*32 + (i >> 1)*16 + t4*4];
            uint32_t bf[2];
            #pragma unroll
            for (int r = 0; r < 2; r++)
                bf[r] = *(const uint32_t*)(g_vt + ((size_t)bh*32 + nt*8 + g)*1024 + ks*32 + r*16 + t4*4);
            mma_u8s8(c, aa, bf);
        }
        if (kq > 0) {
            #pragma unroll
            for (int i = 0; i < 4; i++)
                red[((kq - 1)*4 + nt)*128 + lane*4 + i] = c[i];
        }
        __syncthreads();
        if (kq == 0) {
            #pragma unroll
            for (int idx = 0; idx < 4; idx++) {
                int v = c[idx];
                #pragma unroll
                for (int r = 0; r < 3; r++)
                    v += red[(r*4 + nt)*128 + lane*4 + idx];
                int row = qb + g + (idx >> 1)*8;
                int col = nt*8 + t4*2 + (idx & 1);
                g_a[(size_t)(b*TSEQ + row)*64 + h*32 + col] = (int8_t)(v >> 8);
            }
        }
    }
}

// ============================================================================
// Layer-fused FFN megakernel, 16 tokens/block, grid 256, 256 thr.
// ============================================================================
template<bool LAST>
__global__ void ffn_k(const float* __restrict__ anw, const float* __restrict__ fnw,
                      const float* __restrict__ finw, int l) {
    __shared__ __align__(16) int8_t hs[16][80];
    int tid = threadIdx.x, w = tid >> 5, lane = tid & 31, g = lane >> 2, t4 = lane & 3;
    int tbase = blockIdx.x * 16;
    const uint32_t* wl = g_wter + l*WPL;

    // ---- o-proj + residual: 8 warps x 1 n-tile ----
    {
        uint32_t a[2][4];
        load_a<64>(a, g_a + (size_t)tbase*64, 64, 0, g, t4);
        int n0 = w*8;
        int c[4] = {0,0,0,0};
        mma_w<64>(c, a, wl + 3072, n0, g, t4);
        #pragma unroll
        for (int idx = 0; idx < 4; idx++) {
            int y = iclamp(c[idx] >> 6, -128, 127);
            int row = tbase + g + (idx >> 1)*8;
            int col = n0 + t4*2 + (idx & 1);
            g_x[row*64 + col] = (int8_t)(g_x[row*64 + col] + y);
        }
    }
    __syncthreads();
    norm16(tbase, fnw + l*64, hs, w, lane);
    __syncthreads();
    // ---- up-proj + relu: 8 warps x 4 n-tiles ----
    {
        uint32_t a[2][4];
        load_a<64>(a, &hs[0][0], 80, 0, g, t4);
        for (int nt = w*4; nt < w*4 + 4; nt++) {
            int n0 = nt*8;
            int c[4] = {0,0,0,0};
            mma_w<64>(c, a, wl + 4096, n0, g, t4);
            #pragma unroll
            for (int idx = 0; idx < 4; idx++) {
                int y = iclamp(c[idx] >> 6, -128, 127);
                int row = tbase + g + (idx >> 1)*8;
                int col = n0 + t4*2 + (idx & 1);
                g_u[row*256 + col] = (int8_t)max(y, 0);
            }
        }
    }
    __syncthreads();
    // ---- down-proj + residual: 8 warps x 1 n-tile ----
    {
        uint32_t a[8][4];
        load_a<256>(a, g_u + (size_t)tbase*256, 256, 0, g, t4);
        int n0 = w*8;
        int c[4] = {0,0,0,0};
        mma_w<256>(c, a, wl + 8192, n0, g, t4);
        #pragma unroll
        for (int idx = 0; idx < 4; idx++) {
            int y = iclamp(c[idx] >> 6, -128, 127);
            int row = tbase + g + (idx >> 1)*8;
            int col = n0 + t4*2 + (idx & 1);
            g_x[row*64 + col] = (int8_t)(g_x[row*64 + col] + y);
        }
    }
    __syncthreads();
    // ---- next norm (+QKV) or final norm ----
    if (LAST) {
        norm16(tbase, finw, hs, w, lane);
        __syncthreads();
        int tl = tid >> 4, wd = tid & 15;
        ((uint32_t*)(g_h + (size_t)(tbase + tl)*64))[wd] = *(const uint32_t*)&hs[tl][wd*4];
    } else {
        norm16(tbase, anw + (l+1)*64, hs, w, lane);
        __syncthreads();
        qkv_mma16(tbase, g_wter + (l+1)*WPL, hs, w, lane);
    }
}

// ============================================================================
// Logits via IMMA (validated bit-exact)
// ============================================================================
__global__ void logits_mma_k(float* __restrict__ out) {
    int w = threadIdx.x >> 5, lane = threadIdx.x & 31;
    int g = lane >> 2, t4 = lane & 3;
    int tb = blockIdx.y * 128 + w * 16;
    int nb = blockIdx.x * 64;

    uint32_t a[2][4];
    const int8_t* xb = g_h + (size_t)tb * 64;
    #pragma unroll
    for (int ks = 0; ks < 2; ks++)
        #pragma unroll
        for (int i = 0; i < 4; i++) {
            int row = g + (i & 1) * 8;
            int k = ks*32 + (i >> 1)*16 + t4*4;
            a[ks][i] = *(const uint32_t*)(xb + row*64 + k);
        }

    #pragma unroll
    for (int nt = 0; nt < 8; nt++) {
        int n0 = nb + nt*8;
        int chi[4] = {0,0,0,0}, clo[4] = {0,0,0,0};
        #pragma unroll
        for (int ks = 0; ks < 2; ks++) {
            uint32_t bh[2], bl[2];
            #pragma unroll
            for (int r = 0; r < 2; r++) {
                int k = ks*32 + r*16 + t4*4;
                bh[r] = *(const uint32_t*)(g_ehi + (size_t)(n0 + g)*64 + k);
                bl[r] = *(const uint32_t*)(g_elo + (size_t)(n0 + g)*64 + k);
            }
            mma_s8s8(chi, a[ks], bh);
            mma_s8u8(clo, a[ks], bl);
        }
        #pragma unroll
        for (int half = 0; half < 2; half++) {
            int row = tb + g + half*8;
            int col = n0 + t4*2;
            float2 val;
            val.x = __fmul_rn(__int2float_rn(chi[half*2+0]*256 + clo[half*2+0]), 1.220703125e-4f);
            val.y = __fmul_rn(__int2float_rn(chi[half*2+1]*256 + clo[half*2+1]), 1.220703125e-4f);
            *(float2*)(out + (size_t)row*VOC + col) = val;
        }
    }
}

// ============================================================================
extern "C" void kernel_launch(void* const* d_in, const int* in_sizes, int n_in,
                              void* d_out, int out_size) {
    const int*   tokens  = (const int*)  d_in[0];
    const float* tok_emb = (const float*)d_in[1];
    const float* pos_emb = (const float*)d_in[2];
    const float* anw     = (const float*)d_in[3];
    const float* qw      = (const float*)d_in[4];
    const float* kw      = (const float*)d_in[5];
    const float* vw      = (const float*)d_in[6];
    const float* ow      = (const float*)d_in[7];
    const float* fnw     = (const float*)d_in[8];
    const float* upw     = (const float*)d_in[9];
    const float* dnw     = (const float*)d_in[10];
    const float* finw    = (const float*)d_in[11];
    float* out = (float*)d_out;

    cudaFuncSetAttribute(attn_fused_k, cudaFuncAttributeMaxDynamicSharedMemorySize, ATT_SMEM);

    prep_w_k<<<24, 256>>>(qw, kw, vw, ow, upw, dnw);
    prep_emb_k<<<(VOC*64)/256, 256>>>(tok_emb);
    emb_qkv0_k<<<256, 256>>>(tokens, tok_emb, pos_emb, anw);

    for (int l = 0; l < 4; l++) {
        attn_fused_k<<<dim3(64, 8), 512, ATT_SMEM>>>();
        if (l < 3) ffn_k<false><<<256, 256>>>(anw, fnw, finw, l);
        else       ffn_k<true ><<<256, 256>>>(anw, fnw, finw, l);
    }
    logits_mma_k<<<dim3(VOC/64, NTOK/128), 256>>>(out);
}

// round 12
// speedup vs baseline: 6.2370x; 1.1183x over previous
#include <cuda_runtime.h>
#include <cstdint>

// ============================================================================
// ZyboGPT hw-accurate quantized transformer forward, bit-exact integer impl.
// B=4 T=1024 D=64 H=2 HD=32 DFF=256 L=4 V=8192
// R10: composed-LUT softmax (26-entry eaLUT + per-row prob LUT, conflict-free,
//      no ea store-back), merged prep kernel. 11 launches.
// ============================================================================

#define NTOK   4096
#define TSEQ   1024
#define NH     2
#define DFF    256
#define VOC    8192
#define WPL    12288     // u32 words/layer: qkv@0, o@3072, up@4096, down@8192

// attention smem layout
#define SC_STR 1028                          // score row stride (ints)
#define PP_STR 1040                          // prob row stride (bytes)
#define ATT_SC_B   (16*SC_STR*4)             // 65792
#define ATT_PP_B   (16*PP_STR)               // 16640
#define ATT_PLUT_B (16*32)                   // 512
#define ATT_EA_B   (32*4)                    // 128
#define ATT_RED_B  (3*4*32*4*4)              // 6144
#define ATT_SMEM   (ATT_SC_B + ATT_PP_B + ATT_PLUT_B + ATT_EA_B + ATT_RED_B)

__device__ __align__(16) int8_t  g_x [NTOK*64];
__device__ __align__(16) int8_t  g_q [NTOK*64];
__device__ __align__(16) int8_t  g_k [NTOK*64];
__device__ __align__(16) int8_t  g_v [NTOK*64];
__device__ __align__(16) int8_t  g_vt[8*32*1024];     // [b*H+h][d][t]
__device__ __align__(16) int8_t  g_a [NTOK*64];
__device__ __align__(16) int8_t  g_u [NTOK*DFF];
__device__ __align__(16) int8_t  g_h [NTOK*64];
__device__ __align__(16) uint32_t g_wter[4*WPL];
__device__ __align__(16) int8_t  g_ehi[VOC*64];
__device__ __align__(16) uint8_t g_elo[VOC*64];

__device__ __forceinline__ int iclamp(int v, int lo, int hi) { return min(max(v, lo), hi); }

// ---- IMMA wrappers: m16n8k32, row.col, s32 accum ----
__device__ __forceinline__ void mma_s8s8(int* c, const uint32_t* a, const uint32_t* b) {
    asm volatile("mma.sync.aligned.m16n8k32.row.col.s32.s8.s8.s32 "
        "{%0,%1,%2,%3}, {%4,%5,%6,%7}, {%8,%9}, {%0,%1,%2,%3};"
        : "+r"(c[0]), "+r"(c[1]), "+r"(c[2]), "+r"(c[3])
        : "r"(a[0]), "r"(a[1]), "r"(a[2]), "r"(a[3]), "r"(b[0]), "r"(b[1]));
}
__device__ __forceinline__ void mma_s8u8(int* c, const uint32_t* a, const uint32_t* b) {
    asm volatile("mma.sync.aligned.m16n8k32.row.col.s32.s8.u8.s32 "
        "{%0,%1,%2,%3}, {%4,%5,%6,%7}, {%8,%9}, {%0,%1,%2,%3};"
        : "+r"(c[0]), "+r"(c[1]), "+r"(c[2]), "+r"(c[3])
        : "r"(a[0]), "r"(a[1]), "r"(a[2]), "r"(a[3]), "r"(b[0]), "r"(b[1]));
}
__device__ __forceinline__ void mma_u8s8(int* c, const uint32_t* a, const uint32_t* b) {
    asm volatile("mma.sync.aligned.m16n8k32.row.col.s32.u8.s8.s32 "
        "{%0,%1,%2,%3}, {%4,%5,%6,%7}, {%8,%9}, {%0,%1,%2,%3};"
        : "+r"(c[0]), "+r"(c[1]), "+r"(c[2]), "+r"(c[3])
        : "r"(a[0]), "r"(a[1]), "r"(a[2]), "r"(a[3]), "r"(b[0]), "r"(b[1]));
}

template<int KIN>
__device__ __forceinline__ void load_a(uint32_t a[][4], const int8_t* src, int ldm,
                                       int mt, int g, int t4) {
    #pragma unroll
    for (int ks = 0; ks < KIN/32; ks++)
        #pragma unroll
        for (int i = 0; i < 4; i++) {
            int row = mt*16 + g + (i & 1)*8;
            int k = ks*32 + (i >> 1)*16 + t4*4;
            a[ks][i] = *(const uint32_t*)(src + (size_t)row*ldm + k);
        }
}

template<int KIN>
__device__ __forceinline__ void mma_w(int c[4], const uint32_t a[][4],
                                      const uint32_t* wb, int n0, int g, int t4) {
    #pragma unroll
    for (int ks = 0; ks < KIN/32; ks++) {
        uint32_t bf[2];
        #pragma unroll
        for (int r = 0; r < 2; r++)
            bf[r] = wb[(n0 + g)*(KIN/4) + ks*8 + r*4 + t4];
        mma_s8s8(c, a[ks], bf);
    }
}

// hw PWL exp segment (sh <= 0 always)
__device__ __forceinline__ int pwl_ea(int sh) {
    if (sh >= -3)  return 256 + sh*64;
    if (sh >= -8)  return sh*11 + 97;
    if (sh >= -24) return sh + 24;
    return 0;
}

// ============================================================================
// rmsnorm of 16 tokens into hs[16][80]. 8 warps x 2 tokens.
// ============================================================================
__device__ __forceinline__ void norm16(int tbase, const float* __restrict__ nw,
                                       int8_t hs[16][80], int w, int lane) {
    #pragma unroll
    for (int i = 0; i < 2; i++) {
        int tl = w*2 + i, t = tbase + tl;
        int x0 = g_x[t*64 + lane], x1 = g_x[t*64 + lane + 32];
        int sq = x0*x0 + x1*x1;
        #pragma unroll
        for (int o = 16; o; o >>= 1) sq += __shfl_xor_sync(0xffffffffu, sq, o);
        int lut = min(sq >> 12, 255);
        float bc = (float)(lut*64 + 32);
        int inv = iclamp((int)rintf(__fdiv_rn(16384.0f, __fsqrt_rn(bc))), 0, 16383);
        #pragma unroll
        for (int jj = 0; jj < 2; jj++) {
            int d = lane + jj*32;
            int xi = jj ? x1 : x0;
            int p1 = (xi * inv) >> 8;
            float wc = fminf(fmaxf(nw[d], -2.0f), 2.0f);
            int gq = iclamp((int)rintf(__fmul_rn(wc, 1024.0f)), -32768, 32767);
            float prod = __fmul_rn(__int2float_rn(p1), __int2float_rn(gq));
            int y = (int)floorf(__fmul_rn(prod, 0.0009765625f));
            hs[tl][d] = (int8_t)iclamp(y, -128, 127);
        }
    }
}

// QKV projection for 16 tokens. 8 warps x 3 n-tiles.
__device__ __forceinline__ void qkv_mma16(int tbase, const uint32_t* wl,
                                          int8_t hs[16][80], int w, int lane) {
    int g = lane >> 2, t4 = lane & 3;
    uint32_t a[2][4];
    load_a<64>(a, &hs[0][0], 80, 0, g, t4);
    for (int nt = w*3; nt < w*3 + 3; nt++) {
        int n0 = nt*8;
        int c[4] = {0,0,0,0};
        mma_w<64>(c, a, wl, n0, g, t4);
        #pragma unroll
        for (int idx = 0; idx < 4; idx++) {
            int y = iclamp(c[idx] >> 6, -128, 127);
            int row = tbase + g + (idx >> 1)*8;
            int col = n0 + t4*2 + (idx & 1);
            if (col < 64)       g_q[row*64 + col] = (int8_t)y;
            else if (col < 128) g_k[row*64 + col - 64] = (int8_t)y;
            else {
                int oo = col - 128;
                g_v[row*64 + oo] = (int8_t)y;
                g_vt[((row >> 10)*2 + (oo >> 5))*32768 + (oo & 31)*1024 + (row & 1023)] = (int8_t)y;
            }
        }
    }
}

// ============================================================================
// Merged prep: blocks 0..23 ternarize weights; blocks 24.. split embedding.
// ============================================================================
__global__ void prep_k(const float* __restrict__ qw, const float* __restrict__ kw,
                       const float* __restrict__ vw, const float* __restrict__ ow,
                       const float* __restrict__ upw, const float* __restrict__ dnw,
                       const float* __restrict__ temb) {
    int tid = threadIdx.x;
    if (blockIdx.x >= 24) {
        int i = (blockIdx.x - 24) * 256 + tid;
        int q = iclamp((int)rintf(__fmul_rn(temb[i], 1024.0f)), -32768, 32767);
        g_ehi[i] = (int8_t)(q >> 8);
        g_elo[i] = (uint8_t)(q & 255);
        return;
    }
    int id = blockIdx.x, l = id / 6, mt = id % 6;
    const float* w; int N; uint32_t* dst;
    switch (mt) {
        case 0: w = qw  + l*4096;  N = 4096;  dst = g_wter + l*WPL + 0;    break;
        case 1: w = kw  + l*4096;  N = 4096;  dst = g_wter + l*WPL + 1024; break;
        case 2: w = vw  + l*4096;  N = 4096;  dst = g_wter + l*WPL + 2048; break;
        case 3: w = ow  + l*4096;  N = 4096;  dst = g_wter + l*WPL + 3072; break;
        case 4: w = upw + l*16384; N = 16384; dst = g_wter + l*WPL + 4096; break;
        default:w = dnw + l*16384; N = 16384; dst = g_wter + l*WPL + 8192; break;
    }
    __shared__ float rs[256];
    float s = 0.0f;
    for (int i = tid; i < N; i += 256) s += fabsf(w[i]);
    rs[tid] = s; __syncthreads();
    for (int st = 128; st > 0; st >>= 1) {
        if (tid < st) rs[tid] += rs[tid + st];
        __syncthreads();
    }
    float scale = fmaxf(__fdiv_rn(rs[0], (float)N), 1e-5f);
    for (int wi = tid; wi < N / 4; wi += 256) {
        uint32_t pk = 0;
        #pragma unroll
        for (int j = 0; j < 4; j++) {
            int tv = iclamp((int)rintf(__fdiv_rn(w[wi*4 + j], scale)), -1, 1);
            pk |= ((uint32_t)(tv & 255)) << (8 * j);
        }
        dst[wi] = pk;
    }
}

__global__ void emb_qkv0_k(const int* __restrict__ tokens, const float* __restrict__ temb,
                           const float* __restrict__ pemb, const float* __restrict__ anw) {
    __shared__ __align__(16) int8_t hs[16][80];
    int tid = threadIdx.x, w = tid >> 5, lane = tid & 31;
    int tbase = blockIdx.x * 16;
    for (int i = tid; i < 16*64; i += 256) {
        int tl = i >> 6, d = i & 63, t = tbase + tl;
        int tok = tokens[t];
        int tq = iclamp((int)rintf(__fmul_rn(temb[tok*64 + d], 1024.0f)), -32768, 32767);
        int pq = iclamp((int)rintf(__fmul_rn(pemb[(t & 1023)*64 + d], 1024.0f)), -32768, 32767);
        g_x[t*64 + d] = (int8_t)((tq + pq) >> 3);
    }
    __syncthreads();
    norm16(tbase, anw, hs, w, lane);
    __syncthreads();
    qkv_mma16(tbase, g_wter, hs, w, lane);
}

// ============================================================================
// Fused attention R10. Block = 512 thr, one (bh, 16-row) strip, grid (64 rev, 8).
// Softmax uses: eaLUT[idx] with idx = max(s - (m-25), 0) (block-wide, 26 words,
// conflict-free) for the sum pass, and a composed per-row 26-entry prob LUT
// (consecutive bytes -> conflict-free) for the prob pass. No ea store-back.
// Masks only in the single partial superchunk. Row max >= diag >= 0 so the
// all-masked regime is unreachable; masked/garbage keys -> idx forced 0 -> prob 0.
// ============================================================================
__global__ __launch_bounds__(512, 2) void attn_fused_k() {
    extern __shared__ int sm[];
    int*      sc    = sm;                                 // [16][SC_STR]
    uint8_t*  pp    = (uint8_t*)(sc + 16*SC_STR);         // [16][PP_STR]
    uint8_t*  plut  = pp + 16*PP_STR;                     // [16][32]
    int*      eaLUT = (int*)(plut + 16*32);               // [32]
    int*      red   = eaLUT + 32;                         // [3][4][32][4]

    int tid = threadIdx.x, w = tid >> 5, lane = tid & 31, g = lane >> 2, t4 = lane & 3;
    int qtile = 63 - blockIdx.x;                          // longest strips first
    int bh = blockIdx.y, b = bh >> 1, h = bh & 1;
    int qb = qtile * 16;
    int ntiles = 2*qtile + 2;                             // 8-key n-tiles (= qb+16 keys)
    int nks32 = (qb + 16 + 31) >> 5;                      // 32-key chunks for PV

    if (tid < 26) eaLUT[tid] = pwl_ea(tid - 25);          // visible after phase-1 barrier

    // ---- Phase 1: QK scores into smem ----
    {
        uint32_t a[4];
        #pragma unroll
        for (int i = 0; i < 4; i++) {
            int row = qb + g + (i & 1)*8;
            int k = h*32 + (i >> 1)*16 + t4*4;
            a[i] = *(const uint32_t*)(g_q + (size_t)(b*TSEQ + row)*64 + k);
        }
        for (int nt = w; nt < ntiles; nt += 16) {
            int n0 = nt*8;
            int c[4] = {0,0,0,0};
            uint32_t bf[2];
            #pragma unroll
            for (int r = 0; r < 2; r++)
                bf[r] = *(const uint32_t*)(g_k + (size_t)(b*TSEQ + n0 + g)*64 + h*32 + r*16 + t4*4);
            mma_s8s8(c, a, bf);
            #pragma unroll
            for (int half = 0; half < 2; half++) {
                int rl = g + half*8;
                int2 v;
                v.x = __float2int_rd(__fmul_rn(__fmul_rn(__int2float_rn(c[half*2+0]), 45.0f), 0.00390625f));
                v.y = __float2int_rd(__fmul_rn(__fmul_rn(__int2float_rn(c[half*2+1]), 45.0f), 0.00390625f));
                *(int2*)&sc[rl*SC_STR + n0 + t4*2] = v;
            }
        }
    }
    __syncthreads();

    // ---- Phase 2: softmax, one warp per row ----
    {
        int ql = w, q = qb + ql;
        int* srow = sc + ql*SC_STR;
        int kbase = lane*4;
        int nfull = (q + 1) >> 7;                         // fully-valid superchunks
        int haspart = ((q + 1) & 127) != 0;

        // pass 1: row max (no masks in full chunks)
        int m = -32767;
        for (int sb = 0; sb < nfull; sb++) {
            int4 s4 = *(const int4*)&srow[sb*128 + kbase];
            m = max(m, max(max(s4.x, s4.y), max(s4.z, s4.w)));
        }
        if (haspart) {
            int k0 = nfull*128 + kbase;
            int4 s4 = *(const int4*)&srow[k0];
            if (k0 + 0 > q) s4.x = -32767;
            if (k0 + 1 > q) s4.y = -32767;
            if (k0 + 2 > q) s4.z = -32767;
            if (k0 + 3 > q) s4.w = -32767;
            m = max(m, max(max(s4.x, s4.y), max(s4.z, s4.w)));
        }
        #pragma unroll
        for (int o = 16; o; o >>= 1) m = max(m, __shfl_xor_sync(0xffffffffu, m, o));

        // pass 2: sum of ea via eaLUT (idx clamp; no store-back)
        int mm25 = m - 25;
        int lsum = 0;
        for (int sb = 0; sb < nfull; sb++) {
            int4 s4 = *(const int4*)&srow[sb*128 + kbase];
            lsum += eaLUT[max(s4.x - mm25, 0)] + eaLUT[max(s4.y - mm25, 0)]
                  + eaLUT[max(s4.z - mm25, 0)] + eaLUT[max(s4.w - mm25, 0)];
        }
        if (haspart) {
            int k0 = nfull*128 + kbase;
            int4 s4 = *(const int4*)&srow[k0];
            int i0 = (k0 + 0 > q) ? 0 : max(s4.x - mm25, 0);
            int i1 = (k0 + 1 > q) ? 0 : max(s4.y - mm25, 0);
            int i2 = (k0 + 2 > q) ? 0 : max(s4.z - mm25, 0);
            int i3 = (k0 + 3 > q) ? 0 : max(s4.w - mm25, 0);
            lsum += eaLUT[i0] + eaLUT[i1] + eaLUT[i2] + eaLUT[i3];
        }
        #pragma unroll
        for (int o = 16; o; o >>= 1) lsum += __shfl_xor_sync(0xffffffffu, lsum, o);
        float fs = (float)max(lsum, 1);

        // composed per-row prob LUT: prob(idx) = round(fl(fl(eaLUT[idx]/fs)*255))
        uint8_t* lrow = plut + ql*32;
        if (lane < 26) {
            float p = __fmul_rn(__fdiv_rn((float)eaLUT[lane], fs), 255.0f);
            lrow[lane] = (uint8_t)iclamp((int)rintf(p), 0, 255);
        }
        __syncwarp();

        // pass 3: prob gather straight from scores, pack 4/u32
        uint8_t* prow = pp + ql*PP_STR;
        for (int sb = 0; sb < nfull; sb++) {
            int k0 = sb*128 + kbase;
            int4 s4 = *(const int4*)&srow[k0];
            uint32_t pk = (uint32_t)lrow[max(s4.x - mm25, 0)]
                        | ((uint32_t)lrow[max(s4.y - mm25, 0)] << 8)
                        | ((uint32_t)lrow[max(s4.z - mm25, 0)] << 16)
                        | ((uint32_t)lrow[max(s4.w - mm25, 0)] << 24);
            *(uint32_t*)&prow[k0] = pk;
        }
        if (haspart) {
            int k0 = nfull*128 + kbase;
            int4 s4 = *(const int4*)&srow[k0];
            int i0 = (k0 + 0 > q) ? 0 : max(s4.x - mm25, 0);
            int i1 = (k0 + 1 > q) ? 0 : max(s4.y - mm25, 0);
            int i2 = (k0 + 2 > q) ? 0 : max(s4.z - mm25, 0);
            int i3 = (k0 + 3 > q) ? 0 : max(s4.w - mm25, 0);
            uint32_t pk = (uint32_t)lrow[i0] | ((uint32_t)lrow[i1] << 8)
                        | ((uint32_t)lrow[i2] << 16) | ((uint32_t)lrow[i3] << 24);
            *(uint32_t*)&prow[k0] = pk;
        }
    }
    __syncthreads();

    // ---- Phase 3: PV, warp = (nt dims, kq key-quarter) ----
    {
        int nt = w & 3, kq = w >> 2;
        int c0 = (kq * nks32) >> 2, c1 = ((kq + 1) * nks32) >> 2;
        int c[4] = {0,0,0,0};
        for (int ks = c0; ks < c1; ks++) {
            uint32_t aa[4];
            #pragma unroll
            for (int i = 0; i < 4; i++)
                aa[i] = *(const uint32_t*)&pp[(g + (i & 1)*8)*PP_STR + ks*32 + (i >> 1)*16 + t4*4];
            uint32_t bf[2];
            #pragma unroll
            for (int r = 0; r < 2; r++)
                bf[r] = *(const uint32_t*)(g_vt + ((size_t)bh*32 + nt*8 + g)*1024 + ks*32 + r*16 + t4*4);
            mma_u8s8(c, aa, bf);
        }
        if (kq > 0) {
            #pragma unroll
            for (int i = 0; i < 4; i++)
                red[((kq - 1)*4 + nt)*128 + lane*4 + i] = c[i];
        }
        __syncthreads();
        if (kq == 0) {
            #pragma unroll
            for (int idx = 0; idx < 4; idx++) {
                int v = c[idx];
                #pragma unroll
                for (int r = 0; r < 3; r++)
                    v += red[(r*4 + nt)*128 + lane*4 + idx];
                int row = qb + g + (idx >> 1)*8;
                int col = nt*8 + t4*2 + (idx & 1);
                g_a[(size_t)(b*TSEQ + row)*64 + h*32 + col] = (int8_t)(v >> 8);
            }
        }
    }
}

// ============================================================================
// Layer-fused FFN megakernel, 16 tokens/block, grid 256, 256 thr.
// ============================================================================
template<bool LAST>
__global__ void ffn_k(const float* __restrict__ anw, const float* __restrict__ fnw,
                      const float* __restrict__ finw, int l) {
    __shared__ __align__(16) int8_t hs[16][80];
    int tid = threadIdx.x, w = tid >> 5, lane = tid & 31, g = lane >> 2, t4 = lane & 3;
    int tbase = blockIdx.x * 16;
    const uint32_t* wl = g_wter + l*WPL;

    // ---- o-proj + residual: 8 warps x 1 n-tile ----
    {
        uint32_t a[2][4];
        load_a<64>(a, g_a + (size_t)tbase*64, 64, 0, g, t4);
        int n0 = w*8;
        int c[4] = {0,0,0,0};
        mma_w<64>(c, a, wl + 3072, n0, g, t4);
        #pragma unroll
        for (int idx = 0; idx < 4; idx++) {
            int y = iclamp(c[idx] >> 6, -128, 127);
            int row = tbase + g + (idx >> 1)*8;
            int col = n0 + t4*2 + (idx & 1);
            g_x[row*64 + col] = (int8_t)(g_x[row*64 + col] + y);
        }
    }
    __syncthreads();
    norm16(tbase, fnw + l*64, hs, w, lane);
    __syncthreads();
    // ---- up-proj + relu: 8 warps x 4 n-tiles ----
    {
        uint32_t a[2][4];
        load_a<64>(a, &hs[0][0], 80, 0, g, t4);
        for (int nt = w*4; nt < w*4 + 4; nt++) {
            int n0 = nt*8;
            int c[4] = {0,0,0,0};
            mma_w<64>(c, a, wl + 4096, n0, g, t4);
            #pragma unroll
            for (int idx = 0; idx < 4; idx++) {
                int y = iclamp(c[idx] >> 6, -128, 127);
                int row = tbase + g + (idx >> 1)*8;
                int col = n0 + t4*2 + (idx & 1);
                g_u[row*256 + col] = (int8_t)max(y, 0);
            }
        }
    }
    __syncthreads();
    // ---- down-proj + residual: 8 warps x 1 n-tile ----
    {
        uint32_t a[8][4];
        load_a<256>(a, g_u + (size_t)tbase*256, 256, 0, g, t4);
        int n0 = w*8;
        int c[4] = {0,0,0,0};
        mma_w<256>(c, a, wl + 8192, n0, g, t4);
        #pragma unroll
        for (int idx = 0; idx < 4; idx++) {
            int y = iclamp(c[idx] >> 6, -128, 127);
            int row = tbase + g + (idx >> 1)*8;
            int col = n0 + t4*2 + (idx & 1);
            g_x[row*64 + col] = (int8_t)(g_x[row*64 + col] + y);
        }
    }
    __syncthreads();
    // ---- next norm (+QKV) or final norm ----
    if (LAST) {
        norm16(tbase, finw, hs, w, lane);
        __syncthreads();
        int tl = tid >> 4, wd = tid & 15;
        ((uint32_t*)(g_h + (size_t)(tbase + tl)*64))[wd] = *(const uint32_t*)&hs[tl][wd*4];
    } else {
        norm16(tbase, anw + (l+1)*64, hs, w, lane);
        __syncthreads();
        qkv_mma16(tbase, g_wter + (l+1)*WPL, hs, w, lane);
    }
}

// ============================================================================
// Logits via IMMA (validated bit-exact)
// ============================================================================
__global__ void logits_mma_k(float* __restrict__ out) {
    int w = threadIdx.x >> 5, lane = threadIdx.x & 31;
    int g = lane >> 2, t4 = lane & 3;
    int tb = blockIdx.y * 128 + w * 16;
    int nb = blockIdx.x * 64;

    uint32_t a[2][4];
    const int8_t* xb = g_h + (size_t)tb * 64;
    #pragma unroll
    for (int ks = 0; ks < 2; ks++)
        #pragma unroll
        for (int i = 0; i < 4; i++) {
            int row = g + (i & 1) * 8;
            int k = ks*32 + (i >> 1)*16 + t4*4;
            a[ks][i] = *(const uint32_t*)(xb + row*64 + k);
        }

    #pragma unroll
    for (int nt = 0; nt < 8; nt++) {
        int n0 = nb + nt*8;
        int chi[4] = {0,0,0,0}, clo[4] = {0,0,0,0};
        #pragma unroll
        for (int ks = 0; ks < 2; ks++) {
            uint32_t bh[2], bl[2];
            #pragma unroll
            for (int r = 0; r < 2; r++) {
                int k = ks*32 + r*16 + t4*4;
                bh[r] = *(const uint32_t*)(g_ehi + (size_t)(n0 + g)*64 + k);
                bl[r] = *(const uint32_t*)(g_elo + (size_t)(n0 + g)*64 + k);
            }
            mma_s8s8(chi, a[ks], bh);
            mma_s8u8(clo, a[ks], bl);
        }
        #pragma unroll
        for (int half = 0; half < 2; half++) {
            int row = tb + g + half*8;
            int col = n0 + t4*2;
            float2 val;
            val.x = __fmul_rn(__int2float_rn(chi[half*2+0]*256 + clo[half*2+0]), 1.220703125e-4f);
            val.y = __fmul_rn(__int2float_rn(chi[half*2+1]*256 + clo[half*2+1]), 1.220703125e-4f);
            *(float2*)(out + (size_t)row*VOC + col) = val;
        }
    }
}

// ============================================================================
extern "C" void kernel_launch(void* const* d_in, const int* in_sizes, int n_in,
                              void* d_out, int out_size) {
    const int*   tokens  = (const int*)  d_in[0];
    const float* tok_emb = (const float*)d_in[1];
    const float* pos_emb = (const float*)d_in[2];
    const float* anw     = (const float*)d_in[3];
    const float* qw      = (const float*)d_in[4];
    const float* kw      = (const float*)d_in[5];
    const float* vw      = (const float*)d_in[6];
    const float* ow      = (const float*)d_in[7];
    const float* fnw     = (const float*)d_in[8];
    const float* upw     = (const float*)d_in[9];
    const float* dnw     = (const float*)d_in[10];
    const float* finw    = (const float*)d_in[11];
    float* out = (float*)d_out;

    cudaFuncSetAttribute(attn_fused_k, cudaFuncAttributeMaxDynamicSharedMemorySize, ATT_SMEM);

    prep_k<<<24 + (VOC*64)/256, 256>>>(qw, kw, vw, ow, upw, dnw, tok_emb);
    emb_qkv0_k<<<256, 256>>>(tokens, tok_emb, pos_emb, anw);

    for (int l = 0; l < 4; l++) {
        attn_fused_k<<<dim3(64, 8), 512, ATT_SMEM>>>();
        if (l < 3) ffn_k<false><<<256, 256>>>(anw, fnw, finw, l);
        else       ffn_k<true ><<<256, 256>>>(anw, fnw, finw, l);
    }
    logits_mma_k<<<dim3(VOC/64, NTOK/128), 256>>>(out);
}